// round 9
// baseline (speedup 1.0000x reference)
#include <cuda_runtime.h>
#include <math.h>

#define NN 6000
#define EE 192000
#define MAXDEG 128
#define BN_EPS 1e-5f
#define TR 16
#define GB16 375
#define GB64 94
#define NNINV (1.0f/6000.0f)
#define ASTR 17

// ---------------- scratch ----------------
__device__ int   g_cnt[NN];
__device__ int   g_slot[NN * MAXDEG];
__device__ float g_x0[NN * 64];
__device__ float g_aggA[NN * 64];
__device__ float g_aggB[NN * 64];
__device__ float g_p1[NN * 64];
__device__ float g_p2[NN * 64];
__device__ float g_p3[NN * 4];
__device__ float g_e1[NN * 64];
__device__ float g_e2[NN * 64];
__device__ float g_e3[NN * 64];
__device__ float g_wt[10 * 4096];
__device__ float g_stats[6][2][64];
__device__ float g_ssm[NN * 4];
__device__ int   g_am[NN];
__device__ float g_xemb[NN * 32];
__device__ float g_sx[4 * 192];
__device__ float g_sx2[4 * 16];

__device__ __forceinline__ void bn_coef(int slot, int c, float& s, float& t) {
    float m = g_stats[slot][0][c] * NNINV;
    float v = g_stats[slot][1][c] * NNINV - m * m;
    float sc = rsqrtf(fmaxf(v, 0.f) + BN_EPS);
    s = sc; t = -m * sc;
}

__global__ void k_init(const float* w0, const float* w1, const float* w2,
                       const float* w3, const float* w4, const float* w5,
                       const float* w6, const float* w7, const float* w8,
                       const float* w9) {
    int b = blockIdx.x;
    if (b < 30) {
        int i = b * 256 + threadIdx.x;
        if (i < NN) g_cnt[i] = 0;
        else if (i < NN + 768) ((float*)g_stats)[i - NN] = 0.f;
        else if (i < NN + 1536) g_sx[i - NN - 768] = 0.f;
    } else {
        const float* srcs[10] = {w0, w1, w2, w3, w4, w5, w6, w7, w8, w9};
        int bb = b - 30;
        int m = bb >> 4;
        int idx = ((bb & 15) * 256) + threadIdx.x;
        int k = idx >> 6, c = idx & 63;
        g_wt[m * 4096 + idx] = srcs[m][c * 64 + k];
    }
}

__global__ void k_build_gather(const int* __restrict__ ei,
                               const float* __restrict__ emb,
                               const int* __restrict__ nt) {
    int b = blockIdx.x;
    if (b < 750) {
        int e = b * 256 + threadIdx.x;
        int s = ei[e], d = ei[EE + e];
        int pos = atomicAdd(&g_cnt[s], 1);
        if (pos < MAXDEG) g_slot[s * MAXDEG + pos] = d;
    } else {
        int idx = (b - 750) * 256 + threadIdx.x;
        int i = idx >> 6, c = idx & 63;
        g_x0[idx] = emb[nt[i] * 64 + c];
    }
}

// ---------------- mega-parallel agg: one block per node per job --------------
__global__ void __launch_bounds__(64)
k_agg(const float* __restrict__ inA, int slotA, float* __restrict__ outA,
      const float* __restrict__ inB, int slotB, float* __restrict__ outB) {
    bool isA = blockIdx.x < NN;
    int i = isA ? blockIdx.x : blockIdx.x - NN;
    const float* in = isA ? inA : inB;
    float* out = isA ? outA : outB;
    int slot = isA ? slotA : slotB;
    int c = threadIdx.x;

    float s = 1.f, t = 0.f;
    if (slot >= 0) bn_coef(slot, c, s, t);

    int cnt = g_cnt[i];
    if (cnt > MAXDEG) cnt = MAXDEG;
    const int* sl = g_slot + (size_t)i * MAXDEG;
    float a = 0.f;
    int j = 0;
    for (; j + 4 <= cnt; j += 4) {
        int d0 = sl[j], d1 = sl[j+1], d2 = sl[j+2], d3 = sl[j+3];
        float v0 = in[(size_t)d0 * 64 + c];
        float v1 = in[(size_t)d1 * 64 + c];
        float v2 = in[(size_t)d2 * 64 + c];
        float v3 = in[(size_t)d3 * 64 + c];
        a += (v0 + v1) + (v2 + v3);
    }
    for (; j < cnt; j++) a += in[(size_t)sl[j] * 64 + c];
    out[(size_t)i * 64 + c] = (cnt > 0) ? fmaf(a / (float)cnt, s, t) : 0.f;
}

// ---------------- layer 1 GEMM: dual output, identity input BN ---------------
__global__ void __launch_bounds__(128)
k_gemm_l1(const float* __restrict__ pb, const float* __restrict__ eb) {
    const float* pwr = g_wt + 0 * 4096;
    const float* pwl = g_wt + 1 * 4096;
    const float* ewr = g_wt + 2 * 4096;
    const float* ewl = g_wt + 3 * 4096;
    __shared__ float ash[64 * ASTR];
    __shared__ float xsh[64 * ASTR];
    __shared__ float sum_p[64], sq_p[64], sum_e[64], sq_e[64];
    int tid = threadIdx.x;
    int row0 = blockIdx.x * TR;

    if (tid < 64) {
        sum_p[tid] = 0.f; sq_p[tid] = 0.f; sum_e[tid] = 0.f; sq_e[tid] = 0.f;
    }
    for (int idx = tid; idx < TR * 64; idx += 128) {
        int k = idx & 63, rr = idx >> 6;
        int gr = row0 + rr;
        ash[k * ASTR + rr] = g_aggA[(size_t)gr * 64 + k];
        xsh[k * ASTR + rr] = g_x0[(size_t)gr * 64 + k];
    }
    __syncthreads();

    int cg = tid & 15, rg = tid >> 4;
    int c4 = cg * 4, r2 = rg * 2;
    float accp[2][4] = {}, acce[2][4] = {};
#pragma unroll 4
    for (int k = 0; k < 64; k++) {
        float a0 = ash[k * ASTR + r2];
        float a1 = ash[k * ASTR + r2 + 1];
        float x0 = xsh[k * ASTR + r2];
        float x1 = xsh[k * ASTR + r2 + 1];
        float4 pr = __ldg((const float4*)(pwr + k * 64 + c4));
        float4 pl = __ldg((const float4*)(pwl + k * 64 + c4));
        float4 er = __ldg((const float4*)(ewr + k * 64 + c4));
        float4 el = __ldg((const float4*)(ewl + k * 64 + c4));
        accp[0][0] = fmaf(a0, pr.x, fmaf(x0, pl.x, accp[0][0]));
        accp[0][1] = fmaf(a0, pr.y, fmaf(x0, pl.y, accp[0][1]));
        accp[0][2] = fmaf(a0, pr.z, fmaf(x0, pl.z, accp[0][2]));
        accp[0][3] = fmaf(a0, pr.w, fmaf(x0, pl.w, accp[0][3]));
        accp[1][0] = fmaf(a1, pr.x, fmaf(x1, pl.x, accp[1][0]));
        accp[1][1] = fmaf(a1, pr.y, fmaf(x1, pl.y, accp[1][1]));
        accp[1][2] = fmaf(a1, pr.z, fmaf(x1, pl.z, accp[1][2]));
        accp[1][3] = fmaf(a1, pr.w, fmaf(x1, pl.w, accp[1][3]));
        acce[0][0] = fmaf(a0, er.x, fmaf(x0, el.x, acce[0][0]));
        acce[0][1] = fmaf(a0, er.y, fmaf(x0, el.y, acce[0][1]));
        acce[0][2] = fmaf(a0, er.z, fmaf(x0, el.z, acce[0][2]));
        acce[0][3] = fmaf(a0, er.w, fmaf(x0, el.w, acce[0][3]));
        acce[1][0] = fmaf(a1, er.x, fmaf(x1, el.x, acce[1][0]));
        acce[1][1] = fmaf(a1, er.y, fmaf(x1, el.y, acce[1][1]));
        acce[1][2] = fmaf(a1, er.z, fmaf(x1, el.z, acce[1][2]));
        acce[1][3] = fmaf(a1, er.w, fmaf(x1, el.w, acce[1][3]));
    }
    float psum[4] = {}, psq[4] = {}, esum[4] = {}, esq[4] = {};
#pragma unroll
    for (int ri = 0; ri < 2; ri++) {
        int gr = row0 + r2 + ri;
        float4 op, oe;
        op.x = fmaxf(accp[ri][0] + __ldg(&pb[c4+0]), 0.f);
        op.y = fmaxf(accp[ri][1] + __ldg(&pb[c4+1]), 0.f);
        op.z = fmaxf(accp[ri][2] + __ldg(&pb[c4+2]), 0.f);
        op.w = fmaxf(accp[ri][3] + __ldg(&pb[c4+3]), 0.f);
        oe.x = fmaxf(acce[ri][0] + __ldg(&eb[c4+0]), 0.f);
        oe.y = fmaxf(acce[ri][1] + __ldg(&eb[c4+1]), 0.f);
        oe.z = fmaxf(acce[ri][2] + __ldg(&eb[c4+2]), 0.f);
        oe.w = fmaxf(acce[ri][3] + __ldg(&eb[c4+3]), 0.f);
        *(float4*)&g_p1[(size_t)gr * 64 + c4] = op;
        *(float4*)&g_e1[(size_t)gr * 64 + c4] = oe;
        psum[0]+=op.x; psum[1]+=op.y; psum[2]+=op.z; psum[3]+=op.w;
        psq[0]+=op.x*op.x; psq[1]+=op.y*op.y; psq[2]+=op.z*op.z; psq[3]+=op.w*op.w;
        esum[0]+=oe.x; esum[1]+=oe.y; esum[2]+=oe.z; esum[3]+=oe.w;
        esq[0]+=oe.x*oe.x; esq[1]+=oe.y*oe.y; esq[2]+=oe.z*oe.z; esq[3]+=oe.w*oe.w;
    }
#pragma unroll
    for (int ci = 0; ci < 4; ci++) {
        atomicAdd(&sum_p[c4+ci], psum[ci]); atomicAdd(&sq_p[c4+ci], psq[ci]);
        atomicAdd(&sum_e[c4+ci], esum[ci]); atomicAdd(&sq_e[c4+ci], esq[ci]);
    }
    __syncthreads();
    if (tid < 64) {
        atomicAdd(&g_stats[0][0][tid], sum_p[tid]); atomicAdd(&g_stats[0][1][tid], sq_p[tid]);
        atomicAdd(&g_stats[3][0][tid], sum_e[tid]); atomicAdd(&g_stats[3][1][tid], sq_e[tid]);
    }
}

// ---------------- paired GEMM-only layer jobs ----------------
__global__ void __launch_bounds__(128)
k_gemm(const float* inA, int sAin, const float* wrA, const float* wlA,
       const float* bA, float* outA, int sAout,
       const float* inB, int sBin, const float* wrB, const float* wlB,
       const float* bB, float* outB, int sBout, int coutB) {
    bool isA = blockIdx.x < GB16;
    int blk = isA ? blockIdx.x : blockIdx.x - GB16;
    const float* in = isA ? inA : inB;
    const float* agg = isA ? g_aggA : g_aggB;
    int s_in  = isA ? sAin : sBin;
    const float* wr = isA ? wrA : wrB;
    const float* wl = isA ? wlA : wlB;
    const float* bias = isA ? bA : bB;
    float* out = isA ? outA : outB;
    int s_out = isA ? sAout : sBout;
    int cout  = isA ? 64 : coutB;

    __shared__ float ash[64 * ASTR];
    __shared__ float xsh[64 * ASTR];
    __shared__ float sc[64], tc[64], ssum[64], ssq[64];
    int tid = threadIdx.x;
    int row0 = blk * TR;

    if (tid < 64) {
        float s, t; bn_coef(s_in, tid, s, t);
        sc[tid] = s; tc[tid] = t;
        ssum[tid] = 0.f; ssq[tid] = 0.f;
    }
    __syncthreads();

    for (int idx = tid; idx < TR * 64; idx += 128) {
        int k = idx & 63, rr = idx >> 6;
        int gr = row0 + rr;
        ash[k * ASTR + rr] = agg[(size_t)gr * 64 + k];
        xsh[k * ASTR + rr] = fmaf(in[(size_t)gr * 64 + k], sc[k], tc[k]);
    }
    __syncthreads();

    if (cout == 64) {
        int cg = tid & 15, rg = tid >> 4;
        int c4 = cg * 4, r2 = rg * 2;
        float acc[2][4] = {};
#pragma unroll 4
        for (int k = 0; k < 64; k++) {
            float a0 = ash[k * ASTR + r2];
            float a1 = ash[k * ASTR + r2 + 1];
            float x0 = xsh[k * ASTR + r2];
            float x1 = xsh[k * ASTR + r2 + 1];
            float4 w4 = __ldg((const float4*)(wr + k * 64 + c4));
            float4 l4 = __ldg((const float4*)(wl + k * 64 + c4));
            acc[0][0] = fmaf(a0, w4.x, fmaf(x0, l4.x, acc[0][0]));
            acc[0][1] = fmaf(a0, w4.y, fmaf(x0, l4.y, acc[0][1]));
            acc[0][2] = fmaf(a0, w4.z, fmaf(x0, l4.z, acc[0][2]));
            acc[0][3] = fmaf(a0, w4.w, fmaf(x0, l4.w, acc[0][3]));
            acc[1][0] = fmaf(a1, w4.x, fmaf(x1, l4.x, acc[1][0]));
            acc[1][1] = fmaf(a1, w4.y, fmaf(x1, l4.y, acc[1][1]));
            acc[1][2] = fmaf(a1, w4.z, fmaf(x1, l4.z, acc[1][2]));
            acc[1][3] = fmaf(a1, w4.w, fmaf(x1, l4.w, acc[1][3]));
        }
        float csum[4] = {}, csq[4] = {};
#pragma unroll
        for (int ri = 0; ri < 2; ri++) {
            int gr = row0 + r2 + ri;
            float v0 = fmaxf(acc[ri][0] + __ldg(&bias[c4+0]), 0.f);
            float v1 = fmaxf(acc[ri][1] + __ldg(&bias[c4+1]), 0.f);
            float v2 = fmaxf(acc[ri][2] + __ldg(&bias[c4+2]), 0.f);
            float v3 = fmaxf(acc[ri][3] + __ldg(&bias[c4+3]), 0.f);
            float4 o; o.x = v0; o.y = v1; o.z = v2; o.w = v3;
            *(float4*)&out[(size_t)gr * 64 + c4] = o;
            csum[0]+=v0; csum[1]+=v1; csum[2]+=v2; csum[3]+=v3;
            csq[0]+=v0*v0; csq[1]+=v1*v1; csq[2]+=v2*v2; csq[3]+=v3*v3;
        }
#pragma unroll
        for (int ci = 0; ci < 4; ci++) {
            atomicAdd(&ssum[c4+ci], csum[ci]);
            atomicAdd(&ssq[c4+ci], csq[ci]);
        }
        __syncthreads();
        if (tid < 64) {
            atomicAdd(&g_stats[s_out][0][tid], ssum[tid]);
            atomicAdd(&g_stats[s_out][1][tid], ssq[tid]);
        }
    } else {
        if (tid < 64) {
            int r = tid >> 2, c = tid & 3;
            int gr = row0 + r;
            float acc = 0.f;
#pragma unroll 8
            for (int k = 0; k < 64; k++)
                acc = fmaf(ash[k*ASTR+r], __ldg(&wr[c*64 + k]),
                      fmaf(xsh[k*ASTR+r], __ldg(&wl[c*64 + k]), acc));
            float v = fmaxf(acc + __ldg(&bias[c]), 0.f);
            out[(size_t)gr * 4 + c] = v;
            atomicAdd(&ssum[c], v);
            atomicAdd(&ssq[c], v * v);
        }
        __syncthreads();
        if (tid < 4) {
            atomicAdd(&g_stats[s_out][0][tid], ssum[tid]);
            atomicAdd(&g_stats[s_out][1][tid], ssq[tid]);
        }
    }
}

// ---------------- pool assignment + x_embed ----------------
__global__ void k_pool_xemb(const float* __restrict__ plw, const float* __restrict__ plb,
                            const float* __restrict__ ew, const float* __restrict__ eb) {
    __shared__ float ws[192 * 33];
    __shared__ float s1[64], t1[64], s2[64], t2[64], s3[4], t3[4];
    __shared__ float se[192], te[192];
    int tid = threadIdx.x;

    if (blockIdx.x < 750) {
        if (tid < 64)       { float s,t; bn_coef(0, tid, s, t);      s1[tid]=s; t1[tid]=t; }
        else if (tid < 128) { float s,t; bn_coef(1, tid-64, s, t);   s2[tid-64]=s; t2[tid-64]=t; }
        else if (tid < 132) { float s,t; bn_coef(2, tid-128, s, t);  s3[tid-128]=s; t3[tid-128]=t; }
        __syncthreads();
        int i = blockIdx.x * 8 + (tid >> 5);
        int lane = tid & 31;
        float a0 = 0.f, a1 = 0.f, a2 = 0.f, a3 = 0.f;
        for (int k = lane; k < 64; k += 32) {
            float v1 = fmaf(g_p1[(size_t)i*64+k], s1[k], t1[k]);
            float v2 = fmaf(g_p2[(size_t)i*64+k], s2[k], t2[k]);
            a0 += v1 * plw[0*132+k] + v2 * plw[0*132+64+k];
            a1 += v1 * plw[1*132+k] + v2 * plw[1*132+64+k];
            a2 += v1 * plw[2*132+k] + v2 * plw[2*132+64+k];
            a3 += v1 * plw[3*132+k] + v2 * plw[3*132+64+k];
        }
        if (lane < 4) {
            float v3 = fmaf(g_p3[(size_t)i*4+lane], s3[lane], t3[lane]);
            a0 += v3 * plw[0*132+128+lane];
            a1 += v3 * plw[1*132+128+lane];
            a2 += v3 * plw[2*132+128+lane];
            a3 += v3 * plw[3*132+128+lane];
        }
#pragma unroll
        for (int o = 16; o > 0; o >>= 1) {
            a0 += __shfl_xor_sync(0xFFFFFFFFu, a0, o);
            a1 += __shfl_xor_sync(0xFFFFFFFFu, a1, o);
            a2 += __shfl_xor_sync(0xFFFFFFFFu, a2, o);
            a3 += __shfl_xor_sync(0xFFFFFFFFu, a3, o);
        }
        if (lane == 0) {
            float q0 = fmaxf(a0 + plb[0], 0.f), q1 = fmaxf(a1 + plb[1], 0.f);
            float q2 = fmaxf(a2 + plb[2], 0.f), q3 = fmaxf(a3 + plb[3], 0.f);
            int am = 0; float best = q0;
            if (q1 > best) { best = q1; am = 1; }
            if (q2 > best) { best = q2; am = 2; }
            if (q3 > best) { best = q3; am = 3; }
            g_am[i] = am;
            float e0 = expf(q0-best), e1 = expf(q1-best), e2 = expf(q2-best), e3 = expf(q3-best);
            float inv = 1.f / (e0+e1+e2+e3);
            g_ssm[i*4+0] = e0*inv; g_ssm[i*4+1] = e1*inv;
            g_ssm[i*4+2] = e2*inv; g_ssm[i*4+3] = e3*inv;
        }
    } else {
        if (tid < 192) {
            float s, t; bn_coef(3 + tid / 64, tid & 63, s, t);
            se[tid] = s; te[tid] = t;
        }
        for (int idx = tid; idx < 6144; idx += 256) {
            int c = idx / 192, k = idx % 192;
            ws[k * 33 + c] = ew[idx];
        }
        __syncthreads();
        int blk = blockIdx.x - 750;
        int c = tid & 31, r0t = tid >> 5;
        int row0 = blk * 64;
        for (int r = r0t; r < 64; r += 8) {
            int gr = row0 + r;
            if (gr >= NN) continue;
            float acc = eb[c];
            const float* p1 = &g_e1[(size_t)gr * 64];
            const float* p2 = &g_e2[(size_t)gr * 64];
            const float* p3 = &g_e3[(size_t)gr * 64];
#pragma unroll 8
            for (int k = 0; k < 64; k++) {
                acc = fmaf(fmaf(p1[k], se[k],     te[k]),     ws[k*33+c],       acc);
                acc = fmaf(fmaf(p2[k], se[64+k],  te[64+k]),  ws[(64+k)*33+c],  acc);
                acc = fmaf(fmaf(p3[k], se[128+k], te[128+k]), ws[(128+k)*33+c], acc);
            }
            g_xemb[(size_t)gr * 32 + c] = acc;
        }
    }
}

__global__ void k_sxacc() {
    int c = threadIdx.x;
    int slot = 3 + c / 64, co = c & 63;
    float s, t; bn_coef(slot, co, s, t);
    const float* src = (c < 64) ? g_e1 : (c < 128) ? g_e2 : g_e3;
    int n0 = blockIdx.x * 24;
    float a0 = 0.f, a1 = 0.f, a2 = 0.f, a3 = 0.f;
#pragma unroll 4
    for (int n = n0; n < n0 + 24; n++) {
        float4 w = *(const float4*)&g_ssm[(size_t)n * 4];
        float v = fmaf(src[(size_t)n * 64 + co], s, t);
        a0 = fmaf(w.x, v, a0); a1 = fmaf(w.y, v, a1);
        a2 = fmaf(w.z, v, a2); a3 = fmaf(w.w, v, a3);
    }
    atomicAdd(&g_sx[0*192+c], a0);
    atomicAdd(&g_sx[1*192+c], a1);
    atomicAdd(&g_sx[2*192+c], a2);
    atomicAdd(&g_sx[3*192+c], a3);
}

__global__ void k_head(const float* __restrict__ l1w, const float* __restrict__ l1b,
                       const float* __restrict__ l2w, const float* __restrict__ l2b) {
    __shared__ float t1[4][64];
    int tid = threadIdx.x;
    int j = tid >> 6, c = tid & 63;
    float acc = l1b[c];
#pragma unroll 8
    for (int k = 0; k < 192; k++) acc = fmaf(g_sx[j*192+k], l1w[c*192+k], acc);
    t1[j][c] = fmaxf(acc, 0.f);
    __syncthreads();
    if (tid < 64) {
        int jj = tid >> 4, cc = tid & 15;
        float a = l2b[cc];
#pragma unroll
        for (int k = 0; k < 64; k++) a = fmaf(t1[jj][k], l2w[cc*64+k], a);
        g_sx2[jj*16+cc] = a;
    }
}

__global__ void k_final(const float* __restrict__ l3w, const float* __restrict__ l3b,
                        float* __restrict__ out) {
    __shared__ float w[768];
    __shared__ float b[16];
    __shared__ float sx2[64];
    int tid = threadIdx.x;
    for (int idx = tid; idx < 768; idx += 256) w[idx] = l3w[idx];
    if (tid < 16) b[tid] = l3b[tid];
    if (tid < 64) sx2[tid] = g_sx2[tid];
    __syncthreads();
    int c = tid & 15, ln = tid >> 4;
    int i = blockIdx.x * 16 + ln;
    int am = g_am[i];
    float acc = b[c];
    const float* xe = &g_xemb[(size_t)i * 32];
#pragma unroll
    for (int k = 0; k < 32; k++) acc = fmaf(xe[k], w[c*48+k], acc);
#pragma unroll
    for (int k = 0; k < 16; k++) acc = fmaf(sx2[am*16+k], w[c*48+32+k], acc);
    out[(size_t)i * 16 + c] = acc;
}

// ---------------- host ----------------
extern "C" void kernel_launch(void* const* d_in, const int* in_sizes, int n_in,
                              void* d_out, int out_size) {
    const int* ei = nullptr;
    const int* nt = nullptr;
    const float* P[29];
    int np = 0;
    for (int i = 0; i < n_in; i++) {
        if (in_sizes[i] == 2 * EE)      ei = (const int*)d_in[i];
        else if (in_sizes[i] == NN)     nt = (const int*)d_in[i];
        else if (np < 29)               P[np++] = (const float*)d_in[i];
    }
    if (!ei || !nt || np != 29) return;

    const float *emb  = P[0];
    const float *pw1r = P[1],  *pw1l = P[2],  *pb1 = P[3];
    const float *pw2r = P[4],  *pw2l = P[5],  *pb2 = P[6];
    const float *pw3r = P[7],  *pw3l = P[8],  *pb3 = P[9];
    const float *plw  = P[10], *plb  = P[11];
    const float *ew1r = P[12], *ew1l = P[13], *eb1 = P[14];
    const float *ew2r = P[15], *ew2l = P[16], *eb2 = P[17];
    const float *ew3r = P[18], *ew3l = P[19], *eb3 = P[20];
    const float *l1w  = P[21], *l1b  = P[22];
    const float *l2w  = P[23], *l2b  = P[24];
    const float *emblw = P[25], *emblb = P[26];
    const float *l3w  = P[27], *l3b  = P[28];
    float* out = (float*)d_out;

    static float *p_x0 = nullptr, *p_p1, *p_p2, *p_p3, *p_e1, *p_e2, *p_e3,
                 *p_wt, *p_aggA, *p_aggB;
    if (!p_x0) {
        cudaGetSymbolAddress((void**)&p_x0, g_x0);
        cudaGetSymbolAddress((void**)&p_p1, g_p1);
        cudaGetSymbolAddress((void**)&p_p2, g_p2);
        cudaGetSymbolAddress((void**)&p_p3, g_p3);
        cudaGetSymbolAddress((void**)&p_e1, g_e1);
        cudaGetSymbolAddress((void**)&p_e2, g_e2);
        cudaGetSymbolAddress((void**)&p_e3, g_e3);
        cudaGetSymbolAddress((void**)&p_wt, g_wt);
        cudaGetSymbolAddress((void**)&p_aggA, g_aggA);
        cudaGetSymbolAddress((void**)&p_aggB, g_aggB);
    }

    k_init<<<190, 256>>>(pw1r, pw1l, ew1r, ew1l, pw2r, pw2l, ew2r, ew2l, ew3r, ew3l);
    k_build_gather<<<2250, 256>>>(ei, emb, nt);

    // layer 1: single agg (identity BN), dual-output GEMM
    k_agg<<<NN, 64>>>(p_x0, -1, p_aggA, p_x0, -1, p_aggA);
    k_gemm_l1<<<GB16, 128>>>(pb1, eb1);

    // layer 2: agg both jobs (p1->A slot0, e1->B slot3), paired GEMM
    k_agg<<<2 * NN, 64>>>(p_p1, 0, p_aggA, p_e1, 3, p_aggB);
    k_gemm<<<2 * GB16, 128>>>(p_p1, 0, p_wt + 4*4096, p_wt + 5*4096, pb2, p_p2, 1,
                              p_e1, 3, p_wt + 6*4096, p_wt + 7*4096, eb2, p_e2, 4, 64);

    // layer 3: agg both jobs (e2->A slot4, p2->B slot1), paired GEMM (B cout=4)
    k_agg<<<2 * NN, 64>>>(p_e2, 4, p_aggA, p_p2, 1, p_aggB);
    k_gemm<<<2 * GB16, 128>>>(p_e2, 4, p_wt + 8*4096, p_wt + 9*4096, eb3, p_e3, 5,
                              p_p2, 1, pw3r, pw3l, pb3, p_p3, 2, 4);

    k_pool_xemb<<<750 + GB64, 256>>>(plw, plb, emblw, emblb);
    k_sxacc<<<250, 192>>>();
    k_head<<<1, 256>>>(l1w, l1b, l2w, l2b);
    k_final<<<NN / 16, 256>>>(l3w, l3b, out);
}

// round 10
// speedup vs baseline: 1.2595x; 1.2595x over previous
#include <cuda_runtime.h>
#include <math.h>

#define NN 6000
#define EE 192000
#define MAXDEG 128
#define BN_EPS 1e-5f
#define TR 16                // rows per tile
#define GB16 375             // NN / TR
#define NNINV (1.0f/6000.0f)
#define ASTR 17              // smem stride for 16-row tiles

// ---------------- scratch ----------------
__device__ int   g_cnt[NN];
__device__ int   g_slot[NN * MAXDEG];
__device__ float g_x0[NN * 64];
__device__ float g_p1[NN * 64];   // RAW (pre-BN) activations
__device__ float g_p2[NN * 64];
__device__ float g_p3[NN * 4];
__device__ float g_e1[NN * 64];
__device__ float g_e2[NN * 64];
__device__ float g_e3[NN * 64];
__device__ float g_wt[10 * 4096 + 6144]; // 10 transposed 64x64 + embl_w^T [192][32]
__device__ float g_stats[6][2][64];
__device__ float g_ssm[NN * 4];
__device__ int   g_am[NN];
__device__ float g_xemb[NN * 32];
__device__ float g_sx[4 * 192];
__device__ float g_sx2[4 * 16];

__device__ __forceinline__ void bn_coef(int slot, int c, float& s, float& t) {
    float m = g_stats[slot][0][c] * NNINV;
    float v = g_stats[slot][1][c] * NNINV - m * m;
    float sc = rsqrtf(fmaxf(v, 0.f) + BN_EPS);
    s = sc; t = -m * sc;
}

// ---------------- setup: zero + weight transposes ----------------
// blocks [0,30): zero. [30,190): 10x 64x64 transpose. [190,214): embl_w^T (192x32).
__global__ void k_init(const float* w0, const float* w1, const float* w2,
                       const float* w3, const float* w4, const float* w5,
                       const float* w6, const float* w7, const float* w8,
                       const float* w9, const float* wemb) {
    int b = blockIdx.x;
    if (b < 30) {
        int i = b * 256 + threadIdx.x;
        if (i < NN) g_cnt[i] = 0;
        else if (i < NN + 768) ((float*)g_stats)[i - NN] = 0.f;
        else if (i < NN + 1536) g_sx[i - NN - 768] = 0.f;
    } else if (b < 190) {
        const float* srcs[10] = {w0, w1, w2, w3, w4, w5, w6, w7, w8, w9};
        int bb = b - 30;
        int m = bb >> 4;
        int idx = ((bb & 15) * 256) + threadIdx.x;   // output index, [k][c]
        int k = idx >> 6, c = idx & 63;
        g_wt[m * 4096 + idx] = srcs[m][c * 64 + k];
    } else {
        int idx = (b - 190) * 256 + threadIdx.x;     // [0, 6144)
        int k = idx >> 5, c = idx & 31;              // [k][c], k<192, c<32
        g_wt[10 * 4096 + idx] = wemb[c * 192 + k];
    }
}

__global__ void k_build_gather(const int* __restrict__ ei,
                               const float* __restrict__ emb,
                               const int* __restrict__ nt) {
    int b = blockIdx.x;
    if (b < 750) {
        int e = b * 256 + threadIdx.x;
        int s = ei[e], d = ei[EE + e];
        int pos = atomicAdd(&g_cnt[s], 1);
        if (pos < MAXDEG) g_slot[s * MAXDEG + pos] = d;
    } else {
        int idx = (b - 750) * 256 + threadIdx.x;
        int i = idx >> 6, c = idx & 63;
        g_x0[idx] = emb[nt[i] * 64 + c];
    }
}

// ---------------- agg helper (round-5 verified): 16 rows, 8 thr/row ----------
__device__ __forceinline__ void agg_tile(const float* __restrict__ in, int row0,
                                         float* ash, const float* sc, const float* tc,
                                         int tid) {
    int r = tid >> 3;            // 0..15
    int q = tid & 7;             // channel group
    int gr = row0 + r;
    int cnt = g_cnt[gr];
    if (cnt > MAXDEG) cnt = MAXDEG;
    const int* sl = g_slot + (size_t)gr * MAXDEG;
    int choff = q * 8;
    float4 a0 = {0,0,0,0}, a1 = {0,0,0,0};
    int j = 0;
    for (; j + 2 <= cnt; j += 2) {
        const float4* p0 = (const float4*)(in + (size_t)sl[j]   * 64 + choff);
        const float4* p1 = (const float4*)(in + (size_t)sl[j+1] * 64 + choff);
        float4 u0 = p0[0], u1 = p0[1];
        float4 v0 = p1[0], v1 = p1[1];
        a0.x += u0.x + v0.x; a0.y += u0.y + v0.y;
        a0.z += u0.z + v0.z; a0.w += u0.w + v0.w;
        a1.x += u1.x + v1.x; a1.y += u1.y + v1.y;
        a1.z += u1.z + v1.z; a1.w += u1.w + v1.w;
    }
    if (j < cnt) {
        const float4* p0 = (const float4*)(in + (size_t)sl[j] * 64 + choff);
        float4 u0 = p0[0], u1 = p0[1];
        a0.x += u0.x; a0.y += u0.y; a0.z += u0.z; a0.w += u0.w;
        a1.x += u1.x; a1.y += u1.y; a1.z += u1.z; a1.w += u1.w;
    }
    float vals[8] = {a0.x, a0.y, a0.z, a0.w, a1.x, a1.y, a1.z, a1.w};
    if (cnt > 0) {
        float inv = 1.f / (float)cnt;
#pragma unroll
        for (int u = 0; u < 8; u++) {
            int ch = choff + u;
            ash[ch * ASTR + r] = fmaf(vals[u] * inv, sc[ch], tc[ch]);
        }
    } else {
#pragma unroll
        for (int u = 0; u < 8; u++) ash[(choff + u) * ASTR + r] = 0.f;
    }
}

// ---------------- layer 1: dual output from one agg (round-5) ----------------
__global__ void __launch_bounds__(128)
k_layer1(const float* __restrict__ pb, const float* __restrict__ eb) {
    const float* pwr = g_wt + 0 * 4096;
    const float* pwl = g_wt + 1 * 4096;
    const float* ewr = g_wt + 2 * 4096;
    const float* ewl = g_wt + 3 * 4096;
    __shared__ float ash[64 * ASTR];
    __shared__ float xsh[64 * ASTR];
    __shared__ float idc[64];
    __shared__ float zc[64];
    __shared__ float sum_p[64], sq_p[64], sum_e[64], sq_e[64];
    int tid = threadIdx.x;
    int row0 = blockIdx.x * TR;

    if (tid < 64) {
        idc[tid] = 1.f; zc[tid] = 0.f;
        sum_p[tid] = 0.f; sq_p[tid] = 0.f; sum_e[tid] = 0.f; sq_e[tid] = 0.f;
    }
    __syncthreads();

    agg_tile(g_x0, row0, ash, idc, zc, tid);
    for (int idx = tid; idx < TR * 64; idx += 128) {
        int k = idx & 63, rr = idx >> 6;
        xsh[k * ASTR + rr] = g_x0[(size_t)(row0 + rr) * 64 + k];
    }
    __syncthreads();

    int cg = tid & 15, rg = tid >> 4;     // 16 colgroups x 8 rowgroups
    int c4 = cg * 4, r2 = rg * 2;
    float accp[2][4] = {}, acce[2][4] = {};
#pragma unroll 4
    for (int k = 0; k < 64; k++) {
        float a0 = ash[k * ASTR + r2];
        float a1 = ash[k * ASTR + r2 + 1];
        float x0 = xsh[k * ASTR + r2];
        float x1 = xsh[k * ASTR + r2 + 1];
        float4 pr = __ldg((const float4*)(pwr + k * 64 + c4));
        float4 pl = __ldg((const float4*)(pwl + k * 64 + c4));
        float4 er = __ldg((const float4*)(ewr + k * 64 + c4));
        float4 el = __ldg((const float4*)(ewl + k * 64 + c4));
        accp[0][0] = fmaf(a0, pr.x, fmaf(x0, pl.x, accp[0][0]));
        accp[0][1] = fmaf(a0, pr.y, fmaf(x0, pl.y, accp[0][1]));
        accp[0][2] = fmaf(a0, pr.z, fmaf(x0, pl.z, accp[0][2]));
        accp[0][3] = fmaf(a0, pr.w, fmaf(x0, pl.w, accp[0][3]));
        accp[1][0] = fmaf(a1, pr.x, fmaf(x1, pl.x, accp[1][0]));
        accp[1][1] = fmaf(a1, pr.y, fmaf(x1, pl.y, accp[1][1]));
        accp[1][2] = fmaf(a1, pr.z, fmaf(x1, pl.z, accp[1][2]));
        accp[1][3] = fmaf(a1, pr.w, fmaf(x1, pl.w, accp[1][3]));
        acce[0][0] = fmaf(a0, er.x, fmaf(x0, el.x, acce[0][0]));
        acce[0][1] = fmaf(a0, er.y, fmaf(x0, el.y, acce[0][1]));
        acce[0][2] = fmaf(a0, er.z, fmaf(x0, el.z, acce[0][2]));
        acce[0][3] = fmaf(a0, er.w, fmaf(x0, el.w, acce[0][3]));
        acce[1][0] = fmaf(a1, er.x, fmaf(x1, el.x, acce[1][0]));
        acce[1][1] = fmaf(a1, er.y, fmaf(x1, el.y, acce[1][1]));
        acce[1][2] = fmaf(a1, er.z, fmaf(x1, el.z, acce[1][2]));
        acce[1][3] = fmaf(a1, er.w, fmaf(x1, el.w, acce[1][3]));
    }
    float psum[4] = {}, psq[4] = {}, esum[4] = {}, esq[4] = {};
#pragma unroll
    for (int ri = 0; ri < 2; ri++) {
        int gr = row0 + r2 + ri;
        float4 op, oe;
        op.x = fmaxf(accp[ri][0] + __ldg(&pb[c4+0]), 0.f);
        op.y = fmaxf(accp[ri][1] + __ldg(&pb[c4+1]), 0.f);
        op.z = fmaxf(accp[ri][2] + __ldg(&pb[c4+2]), 0.f);
        op.w = fmaxf(accp[ri][3] + __ldg(&pb[c4+3]), 0.f);
        oe.x = fmaxf(acce[ri][0] + __ldg(&eb[c4+0]), 0.f);
        oe.y = fmaxf(acce[ri][1] + __ldg(&eb[c4+1]), 0.f);
        oe.z = fmaxf(acce[ri][2] + __ldg(&eb[c4+2]), 0.f);
        oe.w = fmaxf(acce[ri][3] + __ldg(&eb[c4+3]), 0.f);
        *(float4*)&g_p1[(size_t)gr * 64 + c4] = op;
        *(float4*)&g_e1[(size_t)gr * 64 + c4] = oe;
        psum[0]+=op.x; psum[1]+=op.y; psum[2]+=op.z; psum[3]+=op.w;
        psq[0]+=op.x*op.x; psq[1]+=op.y*op.y; psq[2]+=op.z*op.z; psq[3]+=op.w*op.w;
        esum[0]+=oe.x; esum[1]+=oe.y; esum[2]+=oe.z; esum[3]+=oe.w;
        esq[0]+=oe.x*oe.x; esq[1]+=oe.y*oe.y; esq[2]+=oe.z*oe.z; esq[3]+=oe.w*oe.w;
    }
#pragma unroll
    for (int ci = 0; ci < 4; ci++) {
        atomicAdd(&sum_p[c4+ci], psum[ci]); atomicAdd(&sq_p[c4+ci], psq[ci]);
        atomicAdd(&sum_e[c4+ci], esum[ci]); atomicAdd(&sq_e[c4+ci], esq[ci]);
    }
    __syncthreads();
    if (tid < 64) {
        atomicAdd(&g_stats[0][0][tid], sum_p[tid]); atomicAdd(&g_stats[0][1][tid], sq_p[tid]);
        atomicAdd(&g_stats[3][0][tid], sum_e[tid]); atomicAdd(&g_stats[3][1][tid], sq_e[tid]);
    }
}

// ---------------- paired layer jobs, 16-row tiles (round-5) ------------------
__global__ void __launch_bounds__(128)
k_pair(const float* inA, int sAin, const float* wrA, const float* wlA,
       const float* bA, float* outA, int sAout,
       const float* inB, int sBin, const float* wrB, const float* wlB,
       const float* bB, float* outB, int sBout, int coutB) {
    bool isA = blockIdx.x < GB16;
    int blk = isA ? blockIdx.x : blockIdx.x - GB16;
    const float* in = isA ? inA : inB;
    int s_in  = isA ? sAin : sBin;
    const float* wr = isA ? wrA : wrB;
    const float* wl = isA ? wlA : wlB;
    const float* bias = isA ? bA : bB;
    float* out = isA ? outA : outB;
    int s_out = isA ? sAout : sBout;
    int cout  = isA ? 64 : coutB;

    __shared__ float ash[64 * ASTR];
    __shared__ float xsh[64 * ASTR];
    __shared__ float sc[64], tc[64], ssum[64], ssq[64];
    int tid = threadIdx.x;
    int row0 = blk * TR;

    if (tid < 64) {
        float s, t; bn_coef(s_in, tid, s, t);
        sc[tid] = s; tc[tid] = t;
        ssum[tid] = 0.f; ssq[tid] = 0.f;
    }
    __syncthreads();

    agg_tile(in, row0, ash, sc, tc, tid);
    for (int idx = tid; idx < TR * 64; idx += 128) {
        int k = idx & 63, rr = idx >> 6;
        xsh[k * ASTR + rr] = fmaf(in[(size_t)(row0 + rr) * 64 + k], sc[k], tc[k]);
    }
    __syncthreads();

    if (cout == 64) {
        int cg = tid & 15, rg = tid >> 4;
        int c4 = cg * 4, r2 = rg * 2;
        float acc[2][4] = {};
#pragma unroll 4
        for (int k = 0; k < 64; k++) {
            float a0 = ash[k * ASTR + r2];
            float a1 = ash[k * ASTR + r2 + 1];
            float x0 = xsh[k * ASTR + r2];
            float x1 = xsh[k * ASTR + r2 + 1];
            float4 w4 = __ldg((const float4*)(wr + k * 64 + c4));
            float4 l4 = __ldg((const float4*)(wl + k * 64 + c4));
            acc[0][0] = fmaf(a0, w4.x, fmaf(x0, l4.x, acc[0][0]));
            acc[0][1] = fmaf(a0, w4.y, fmaf(x0, l4.y, acc[0][1]));
            acc[0][2] = fmaf(a0, w4.z, fmaf(x0, l4.z, acc[0][2]));
            acc[0][3] = fmaf(a0, w4.w, fmaf(x0, l4.w, acc[0][3]));
            acc[1][0] = fmaf(a1, w4.x, fmaf(x1, l4.x, acc[1][0]));
            acc[1][1] = fmaf(a1, w4.y, fmaf(x1, l4.y, acc[1][1]));
            acc[1][2] = fmaf(a1, w4.z, fmaf(x1, l4.z, acc[1][2]));
            acc[1][3] = fmaf(a1, w4.w, fmaf(x1, l4.w, acc[1][3]));
        }
        float csum[4] = {}, csq[4] = {};
#pragma unroll
        for (int ri = 0; ri < 2; ri++) {
            int gr = row0 + r2 + ri;
            float v0 = fmaxf(acc[ri][0] + __ldg(&bias[c4+0]), 0.f);
            float v1 = fmaxf(acc[ri][1] + __ldg(&bias[c4+1]), 0.f);
            float v2 = fmaxf(acc[ri][2] + __ldg(&bias[c4+2]), 0.f);
            float v3 = fmaxf(acc[ri][3] + __ldg(&bias[c4+3]), 0.f);
            float4 o; o.x = v0; o.y = v1; o.z = v2; o.w = v3;
            *(float4*)&out[(size_t)gr * 64 + c4] = o;
            csum[0]+=v0; csum[1]+=v1; csum[2]+=v2; csum[3]+=v3;
            csq[0]+=v0*v0; csq[1]+=v1*v1; csq[2]+=v2*v2; csq[3]+=v3*v3;
        }
#pragma unroll
        for (int ci = 0; ci < 4; ci++) {
            atomicAdd(&ssum[c4+ci], csum[ci]);
            atomicAdd(&ssq[c4+ci], csq[ci]);
        }
        __syncthreads();
        if (tid < 64) {
            atomicAdd(&g_stats[s_out][0][tid], ssum[tid]);
            atomicAdd(&g_stats[s_out][1][tid], ssq[tid]);
        }
    } else {
        // cout == 4: 16 rows x 4 cols = 64 active threads; W is (4,64) row-major
        if (tid < 64) {
            int r = tid >> 2, c = tid & 3;
            int gr = row0 + r;
            float acc = 0.f;
#pragma unroll 8
            for (int k = 0; k < 64; k++)
                acc = fmaf(ash[k*ASTR+r], __ldg(&wr[c*64 + k]),
                      fmaf(xsh[k*ASTR+r], __ldg(&wl[c*64 + k]), acc));
            float v = fmaxf(acc + __ldg(&bias[c]), 0.f);
            out[(size_t)gr * 4 + c] = v;
            atomicAdd(&ssum[c], v);
            atomicAdd(&ssq[c], v * v);
        }
        __syncthreads();
        if (tid < 4) {
            atomicAdd(&g_stats[s_out][0][tid], ssum[tid]);
            atomicAdd(&g_stats[s_out][1][tid], ssq[tid]);
        }
    }
}

// ---------------- pool assignment (750 blocks) + x_embed (375 blocks) --------
__global__ void k_pool_xemb(const float* __restrict__ plw, const float* __restrict__ plb,
                            const float* __restrict__ eb) {
    __shared__ float s1[64], t1[64], s2[64], t2[64], s3[4], t3[4];
    __shared__ float se[192], te[192];
    __shared__ float xsh[192 * ASTR];    // xemb branch: 16 rows x 192 ch (BN'd)
    int tid = threadIdx.x;

    if (blockIdx.x < 750) {
        if (tid < 64)       { float s,t; bn_coef(0, tid, s, t);      s1[tid]=s; t1[tid]=t; }
        else if (tid < 128) { float s,t; bn_coef(1, tid-64, s, t);   s2[tid-64]=s; t2[tid-64]=t; }
        else if (tid < 132) { float s,t; bn_coef(2, tid-128, s, t);  s3[tid-128]=s; t3[tid-128]=t; }
        __syncthreads();
        int i = blockIdx.x * 8 + (tid >> 5);
        int lane = tid & 31;
        float a0 = 0.f, a1 = 0.f, a2 = 0.f, a3 = 0.f;
        for (int k = lane; k < 64; k += 32) {
            float v1 = fmaf(g_p1[(size_t)i*64+k], s1[k], t1[k]);
            float v2 = fmaf(g_p2[(size_t)i*64+k], s2[k], t2[k]);
            a0 += v1 * plw[0*132+k] + v2 * plw[0*132+64+k];
            a1 += v1 * plw[1*132+k] + v2 * plw[1*132+64+k];
            a2 += v1 * plw[2*132+k] + v2 * plw[2*132+64+k];
            a3 += v1 * plw[3*132+k] + v2 * plw[3*132+64+k];
        }
        if (lane < 4) {
            float v3 = fmaf(g_p3[(size_t)i*4+lane], s3[lane], t3[lane]);
            a0 += v3 * plw[0*132+128+lane];
            a1 += v3 * plw[1*132+128+lane];
            a2 += v3 * plw[2*132+128+lane];
            a3 += v3 * plw[3*132+128+lane];
        }
#pragma unroll
        for (int o = 16; o > 0; o >>= 1) {
            a0 += __shfl_xor_sync(0xFFFFFFFFu, a0, o);
            a1 += __shfl_xor_sync(0xFFFFFFFFu, a1, o);
            a2 += __shfl_xor_sync(0xFFFFFFFFu, a2, o);
            a3 += __shfl_xor_sync(0xFFFFFFFFu, a3, o);
        }
        if (lane == 0) {
            float q0 = fmaxf(a0 + plb[0], 0.f), q1 = fmaxf(a1 + plb[1], 0.f);
            float q2 = fmaxf(a2 + plb[2], 0.f), q3 = fmaxf(a3 + plb[3], 0.f);
            int am = 0; float best = q0;
            if (q1 > best) { best = q1; am = 1; }
            if (q2 > best) { best = q2; am = 2; }
            if (q3 > best) { best = q3; am = 3; }
            g_am[i] = am;
            float e0 = expf(q0-best), e1 = expf(q1-best), e2 = expf(q2-best), e3 = expf(q3-best);
            float inv = 1.f / (e0+e1+e2+e3);
            g_ssm[i*4+0] = e0*inv; g_ssm[i*4+1] = e1*inv;
            g_ssm[i*4+2] = e2*inv; g_ssm[i*4+3] = e3*inv;
        }
    } else {
        // ---- x_embed: 16 rows, transposed weights from g_wt (no weight stage)
        if (tid < 192) {
            float s, t; bn_coef(3 + tid / 64, tid & 63, s, t);
            se[tid] = s; te[tid] = t;
        }
        __syncthreads();
        int blk = blockIdx.x - 750;          // 0..374
        int row0 = blk * 16;
        // stage BN'd concat(e1,e2,e3) -> xsh[k*ASTR + r], coalesced per source
        for (int idx = tid; idx < 1024; idx += 256) {
            int k = idx & 63, rr = idx >> 6;
            int gr = row0 + rr;
            xsh[k * ASTR + rr]        = fmaf(g_e1[(size_t)gr*64+k], se[k],     te[k]);
            xsh[(64+k) * ASTR + rr]   = fmaf(g_e2[(size_t)gr*64+k], se[64+k],  te[64+k]);
            xsh[(128+k) * ASTR + rr]  = fmaf(g_e3[(size_t)gr*64+k], se[128+k], te[128+k]);
        }
        __syncthreads();
        const float* wtx = g_wt + 10 * 4096;   // [k][c], 192 x 32
        // 256 threads: 16 rows x (8 colgroups of 4) = 128 outputs of 4 -> 2 rows/thread? 
        // use 128 active pairs: tid -> rg = tid>>4 (16 rows), cg = tid&15 -> but 32 cols only 8 groups.
        // Layout: rg = tid >> 3 (0..31 -> only 0..15 valid when tid<128); use tid<128.
        if (tid < 128) {
            int rg = tid >> 3;          // 0..15 row
            int cg = tid & 7;           // 0..7 colgroup of 4
            int c4 = cg * 4;
            float acc0 = __ldg(&eb[c4+0]);
            float acc1 = __ldg(&eb[c4+1]);
            float acc2 = __ldg(&eb[c4+2]);
            float acc3 = __ldg(&eb[c4+3]);
#pragma unroll 8
            for (int k = 0; k < 192; k++) {
                float a = xsh[k * ASTR + rg];
                float4 w4 = __ldg((const float4*)(wtx + k * 32 + c4));
                acc0 = fmaf(a, w4.x, acc0);
                acc1 = fmaf(a, w4.y, acc1);
                acc2 = fmaf(a, w4.z, acc2);
                acc3 = fmaf(a, w4.w, acc3);
            }
            int gr = row0 + rg;
            float4 o; o.x = acc0; o.y = acc1; o.z = acc2; o.w = acc3;
            *(float4*)&g_xemb[(size_t)gr * 32 + c4] = o;
        }
    }
}

// s_x = softmax(S)^T @ BN(XE) -> [4,192], 250 blocks x 24 nodes
__global__ void k_sxacc() {
    int c = threadIdx.x;                  // 0..191
    int slot = 3 + c / 64, co = c & 63;
    float s, t; bn_coef(slot, co, s, t);
    const float* src = (c < 64) ? g_e1 : (c < 128) ? g_e2 : g_e3;
    int n0 = blockIdx.x * 24;
    float a0 = 0.f, a1 = 0.f, a2 = 0.f, a3 = 0.f;
#pragma unroll 4
    for (int n = n0; n < n0 + 24; n++) {
        float4 w = *(const float4*)&g_ssm[(size_t)n * 4];
        float v = fmaf(src[(size_t)n * 64 + co], s, t);
        a0 = fmaf(w.x, v, a0); a1 = fmaf(w.y, v, a1);
        a2 = fmaf(w.z, v, a2); a3 = fmaf(w.w, v, a3);
    }
    atomicAdd(&g_sx[0*192+c], a0);
    atomicAdd(&g_sx[1*192+c], a1);
    atomicAdd(&g_sx[2*192+c], a2);
    atomicAdd(&g_sx[3*192+c], a3);
}

__global__ void k_head(const float* __restrict__ l1w, const float* __restrict__ l1b,
                       const float* __restrict__ l2w, const float* __restrict__ l2b) {
    __shared__ float t1[4][64];
    int tid = threadIdx.x;
    int j = tid >> 6, c = tid & 63;
    float acc = l1b[c];
#pragma unroll 8
    for (int k = 0; k < 192; k++) acc = fmaf(g_sx[j*192+k], l1w[c*192+k], acc);
    t1[j][c] = fmaxf(acc, 0.f);
    __syncthreads();
    if (tid < 64) {
        int jj = tid >> 4, cc = tid & 15;
        float a = l2b[cc];
#pragma unroll
        for (int k = 0; k < 64; k++) a = fmaf(t1[jj][k], l2w[cc*64+k], a);
        g_sx2[jj*16+cc] = a;
    }
}

__global__ void k_final(const float* __restrict__ l3w, const float* __restrict__ l3b,
                        float* __restrict__ out) {
    __shared__ float w[768];
    __shared__ float b[16];
    __shared__ float sx2[64];
    int tid = threadIdx.x;
    for (int idx = tid; idx < 768; idx += 256) w[idx] = l3w[idx];
    if (tid < 16) b[tid] = l3b[tid];
    if (tid < 64) sx2[tid] = g_sx2[tid];
    __syncthreads();
    int c = tid & 15, ln = tid >> 4;
    int i = blockIdx.x * 16 + ln;
    int am = g_am[i];
    float acc = b[c];
    const float* xe = &g_xemb[(size_t)i * 32];
#pragma unroll
    for (int k = 0; k < 32; k++) acc = fmaf(xe[k], w[c*48+k], acc);
#pragma unroll
    for (int k = 0; k < 16; k++) acc = fmaf(sx2[am*16+k], w[c*48+32+k], acc);
    out[(size_t)i * 16 + c] = acc;
}

// ---------------- host ----------------
extern "C" void kernel_launch(void* const* d_in, const int* in_sizes, int n_in,
                              void* d_out, int out_size) {
    const int* ei = nullptr;
    const int* nt = nullptr;
    const float* P[29];
    int np = 0;
    for (int i = 0; i < n_in; i++) {
        if (in_sizes[i] == 2 * EE)      ei = (const int*)d_in[i];
        else if (in_sizes[i] == NN)     nt = (const int*)d_in[i];
        else if (np < 29)               P[np++] = (const float*)d_in[i];
    }
    if (!ei || !nt || np != 29) return;

    const float *emb  = P[0];
    const float *pw1r = P[1],  *pw1l = P[2],  *pb1 = P[3];
    const float *pw2r = P[4],  *pw2l = P[5],  *pb2 = P[6];
    const float *pw3r = P[7],  *pw3l = P[8],  *pb3 = P[9];
    const float *plw  = P[10], *plb  = P[11];
    const float *ew1r = P[12], *ew1l = P[13], *eb1 = P[14];
    const float *ew2r = P[15], *ew2l = P[16], *eb2 = P[17];
    const float *ew3r = P[18], *ew3l = P[19], *eb3 = P[20];
    const float *l1w  = P[21], *l1b  = P[22];
    const float *l2w  = P[23], *l2b  = P[24];
    const float *emblw = P[25], *emblb = P[26];
    const float *l3w  = P[27], *l3b  = P[28];
    float* out = (float*)d_out;

    static float *p_p1 = nullptr, *p_p2, *p_p3, *p_e1, *p_e2, *p_e3, *p_wt;
    if (!p_p1) {
        cudaGetSymbolAddress((void**)&p_p1, g_p1);
        cudaGetSymbolAddress((void**)&p_p2, g_p2);
        cudaGetSymbolAddress((void**)&p_p3, g_p3);
        cudaGetSymbolAddress((void**)&p_e1, g_e1);
        cudaGetSymbolAddress((void**)&p_e2, g_e2);
        cudaGetSymbolAddress((void**)&p_e3, g_e3);
        cudaGetSymbolAddress((void**)&p_wt, g_wt);
    }

    k_init<<<214, 256>>>(pw1r, pw1l, ew1r, ew1l, pw2r, pw2l, ew2r, ew2l,
                         ew3r, ew3l, emblw);
    k_build_gather<<<2250, 256>>>(ei, emb, nt);
    // layer 1: one agg, both outputs
    k_layer1<<<GB16, 128>>>(pb1, eb1);
    // layer 2 (pool + embed), transposed weights from g_wt
    k_pair<<<2 * GB16, 128>>>(p_p1, 0, p_wt + 4*4096, p_wt + 5*4096, pb2, p_p2, 1,
                              p_e1, 3, p_wt + 6*4096, p_wt + 7*4096, eb2, p_e2, 4, 64);
    // layer 3 (embed cout=64 + pool cout=4; pool uses original row-major weights)
    k_pair<<<2 * GB16, 128>>>(p_e2, 4, p_wt + 8*4096, p_wt + 9*4096, eb3, p_e3, 5,
                              p_p2, 1, pw3r, pw3l, pb3, p_p3, 2, 4);
    k_pool_xemb<<<1125, 256>>>(plw, plb, emblb);
    k_sxacc<<<250, 192>>>();
    k_head<<<1, 256>>>(l1w, l1b, l2w, l2b);
    k_final<<<NN / 16, 256>>>(l3w, l3b, out);
}

// round 11
// speedup vs baseline: 1.2691x; 1.0076x over previous
#include <cuda_runtime.h>
#include <math.h>

#define NN 6000
#define EE 192000
#define MAXDEG 128
#define BN_EPS 1e-5f
#define TR 16                // rows per tile
#define GB16 375             // NN / TR
#define NNINV (1.0f/6000.0f)
#define ASTR 17              // smem stride for 16-row tiles

// ---------------- scratch ----------------
__device__ int   g_cnt[NN];
__device__ int   g_slot[NN * MAXDEG];
__device__ float g_x0[NN * 64];
__device__ float g_p1[NN * 64];   // RAW (pre-BN) activations
__device__ float g_p2[NN * 64];
__device__ float g_p3[NN * 4];
__device__ float g_e1[NN * 64];
__device__ float g_e2[NN * 64];
__device__ float g_e3[NN * 64];
__device__ float g_wt[10 * 4096 + 6144]; // 10 transposed 64x64 + embl_w^T [192][32]
__device__ float g_stats[6][2][64];
__device__ float g_ssm[NN * 4];
__device__ int   g_am[NN];
__device__ float g_xemb[NN * 32];
__device__ float g_sx[4 * 192];
__device__ float g_sx2[4 * 16];

__device__ __forceinline__ void bn_coef(int slot, int c, float& s, float& t) {
    float m = g_stats[slot][0][c] * NNINV;
    float v = g_stats[slot][1][c] * NNINV - m * m;
    float sc = rsqrtf(fmaxf(v, 0.f) + BN_EPS);
    s = sc; t = -m * sc;
}

// ---------------- setup: zero + weight transposes ----------------
__global__ void k_init(const float* w0, const float* w1, const float* w2,
                       const float* w3, const float* w4, const float* w5,
                       const float* w6, const float* w7, const float* w8,
                       const float* w9, const float* wemb) {
    int b = blockIdx.x;
    if (b < 30) {
        int i = b * 256 + threadIdx.x;
        if (i < NN) g_cnt[i] = 0;
        else if (i < NN + 768) ((float*)g_stats)[i - NN] = 0.f;
        else if (i < NN + 1536) g_sx[i - NN - 768] = 0.f;
    } else if (b < 190) {
        const float* srcs[10] = {w0, w1, w2, w3, w4, w5, w6, w7, w8, w9};
        int bb = b - 30;
        int m = bb >> 4;
        int idx = ((bb & 15) * 256) + threadIdx.x;   // output index, [k][c]
        int k = idx >> 6, c = idx & 63;
        g_wt[m * 4096 + idx] = srcs[m][c * 64 + k];
    } else {
        int idx = (b - 190) * 256 + threadIdx.x;     // [0, 6144)
        int k = idx >> 5, c = idx & 31;              // [k][c], k<192, c<32
        g_wt[10 * 4096 + idx] = wemb[c * 192 + k];
    }
}

__global__ void k_build_gather(const int* __restrict__ ei,
                               const float* __restrict__ emb,
                               const int* __restrict__ nt) {
    int b = blockIdx.x;
    if (b < 750) {
        int e = b * 256 + threadIdx.x;
        int s = ei[e], d = ei[EE + e];
        int pos = atomicAdd(&g_cnt[s], 1);
        if (pos < MAXDEG) g_slot[s * MAXDEG + pos] = d;
    } else {
        int idx = (b - 750) * 256 + threadIdx.x;
        int i = idx >> 6, c = idx & 63;
        g_x0[idx] = emb[nt[i] * 64 + c];
    }
}

// ---------------- agg helper: 16 rows, 256 threads, 16 thr/row, 4 ch each ----
// Doubled warp count for latency hiding; per-thread loads 1 float4 per edge,
// unrolled 4 edges deep for MLP.
__device__ __forceinline__ void agg_tile256(const float* __restrict__ in, int row0,
                                            float* ash, const float* sc, const float* tc,
                                            int tid) {
    int r = tid >> 4;            // 0..15
    int q = tid & 15;            // channel group of 4
    int gr = row0 + r;
    int cnt = g_cnt[gr];
    if (cnt > MAXDEG) cnt = MAXDEG;
    const int* sl = g_slot + (size_t)gr * MAXDEG;
    int choff = q * 4;
    float4 a = {0, 0, 0, 0};
    int j = 0;
    for (; j + 4 <= cnt; j += 4) {
        int i0 = sl[j], i1 = sl[j+1], i2 = sl[j+2], i3 = sl[j+3];
        float4 u0 = *(const float4*)(in + (size_t)i0 * 64 + choff);
        float4 u1 = *(const float4*)(in + (size_t)i1 * 64 + choff);
        float4 u2 = *(const float4*)(in + (size_t)i2 * 64 + choff);
        float4 u3 = *(const float4*)(in + (size_t)i3 * 64 + choff);
        a.x += (u0.x + u1.x) + (u2.x + u3.x);
        a.y += (u0.y + u1.y) + (u2.y + u3.y);
        a.z += (u0.z + u1.z) + (u2.z + u3.z);
        a.w += (u0.w + u1.w) + (u2.w + u3.w);
    }
    for (; j < cnt; j++) {
        float4 u0 = *(const float4*)(in + (size_t)sl[j] * 64 + choff);
        a.x += u0.x; a.y += u0.y; a.z += u0.z; a.w += u0.w;
    }
    if (cnt > 0) {
        float inv = 1.f / (float)cnt;
        ash[(choff+0) * ASTR + r] = fmaf(a.x * inv, sc[choff+0], tc[choff+0]);
        ash[(choff+1) * ASTR + r] = fmaf(a.y * inv, sc[choff+1], tc[choff+1]);
        ash[(choff+2) * ASTR + r] = fmaf(a.z * inv, sc[choff+2], tc[choff+2]);
        ash[(choff+3) * ASTR + r] = fmaf(a.w * inv, sc[choff+3], tc[choff+3]);
    } else {
#pragma unroll
        for (int u = 0; u < 4; u++) ash[(choff + u) * ASTR + r] = 0.f;
    }
}

// ---------------- layer 1: dual output from one agg ----------------
__global__ void __launch_bounds__(256)
k_layer1(const float* __restrict__ pb, const float* __restrict__ eb) {
    const float* pwr = g_wt + 0 * 4096;
    const float* pwl = g_wt + 1 * 4096;
    const float* ewr = g_wt + 2 * 4096;
    const float* ewl = g_wt + 3 * 4096;
    __shared__ float ash[64 * ASTR];
    __shared__ float xsh[64 * ASTR];
    __shared__ float idc[64];
    __shared__ float zc[64];
    __shared__ float sum_p[64], sq_p[64], sum_e[64], sq_e[64];
    int tid = threadIdx.x;
    int row0 = blockIdx.x * TR;

    if (tid < 64) {
        idc[tid] = 1.f; zc[tid] = 0.f;
        sum_p[tid] = 0.f; sq_p[tid] = 0.f; sum_e[tid] = 0.f; sq_e[tid] = 0.f;
    }
    __syncthreads();

    agg_tile256(g_x0, row0, ash, idc, zc, tid);
    for (int idx = tid; idx < TR * 64; idx += 256) {
        int k = idx & 63, rr = idx >> 6;
        xsh[k * ASTR + rr] = g_x0[(size_t)(row0 + rr) * 64 + k];
    }
    __syncthreads();

    if (tid < 128) {
        int cg = tid & 15, rg = tid >> 4;     // 16 colgroups x 8 rowgroups
        int c4 = cg * 4, r2 = rg * 2;
        float accp[2][4] = {}, acce[2][4] = {};
#pragma unroll 4
        for (int k = 0; k < 64; k++) {
            float a0 = ash[k * ASTR + r2];
            float a1 = ash[k * ASTR + r2 + 1];
            float x0 = xsh[k * ASTR + r2];
            float x1 = xsh[k * ASTR + r2 + 1];
            float4 pr = __ldg((const float4*)(pwr + k * 64 + c4));
            float4 pl = __ldg((const float4*)(pwl + k * 64 + c4));
            float4 er = __ldg((const float4*)(ewr + k * 64 + c4));
            float4 el = __ldg((const float4*)(ewl + k * 64 + c4));
            accp[0][0] = fmaf(a0, pr.x, fmaf(x0, pl.x, accp[0][0]));
            accp[0][1] = fmaf(a0, pr.y, fmaf(x0, pl.y, accp[0][1]));
            accp[0][2] = fmaf(a0, pr.z, fmaf(x0, pl.z, accp[0][2]));
            accp[0][3] = fmaf(a0, pr.w, fmaf(x0, pl.w, accp[0][3]));
            accp[1][0] = fmaf(a1, pr.x, fmaf(x1, pl.x, accp[1][0]));
            accp[1][1] = fmaf(a1, pr.y, fmaf(x1, pl.y, accp[1][1]));
            accp[1][2] = fmaf(a1, pr.z, fmaf(x1, pl.z, accp[1][2]));
            accp[1][3] = fmaf(a1, pr.w, fmaf(x1, pl.w, accp[1][3]));
            acce[0][0] = fmaf(a0, er.x, fmaf(x0, el.x, acce[0][0]));
            acce[0][1] = fmaf(a0, er.y, fmaf(x0, el.y, acce[0][1]));
            acce[0][2] = fmaf(a0, er.z, fmaf(x0, el.z, acce[0][2]));
            acce[0][3] = fmaf(a0, er.w, fmaf(x0, el.w, acce[0][3]));
            acce[1][0] = fmaf(a1, er.x, fmaf(x1, el.x, acce[1][0]));
            acce[1][1] = fmaf(a1, er.y, fmaf(x1, el.y, acce[1][1]));
            acce[1][2] = fmaf(a1, er.z, fmaf(x1, el.z, acce[1][2]));
            acce[1][3] = fmaf(a1, er.w, fmaf(x1, el.w, acce[1][3]));
        }
        float psum[4] = {}, psq[4] = {}, esum[4] = {}, esq[4] = {};
#pragma unroll
        for (int ri = 0; ri < 2; ri++) {
            int gr = row0 + r2 + ri;
            float4 op, oe;
            op.x = fmaxf(accp[ri][0] + __ldg(&pb[c4+0]), 0.f);
            op.y = fmaxf(accp[ri][1] + __ldg(&pb[c4+1]), 0.f);
            op.z = fmaxf(accp[ri][2] + __ldg(&pb[c4+2]), 0.f);
            op.w = fmaxf(accp[ri][3] + __ldg(&pb[c4+3]), 0.f);
            oe.x = fmaxf(acce[ri][0] + __ldg(&eb[c4+0]), 0.f);
            oe.y = fmaxf(acce[ri][1] + __ldg(&eb[c4+1]), 0.f);
            oe.z = fmaxf(acce[ri][2] + __ldg(&eb[c4+2]), 0.f);
            oe.w = fmaxf(acce[ri][3] + __ldg(&eb[c4+3]), 0.f);
            *(float4*)&g_p1[(size_t)gr * 64 + c4] = op;
            *(float4*)&g_e1[(size_t)gr * 64 + c4] = oe;
            psum[0]+=op.x; psum[1]+=op.y; psum[2]+=op.z; psum[3]+=op.w;
            psq[0]+=op.x*op.x; psq[1]+=op.y*op.y; psq[2]+=op.z*op.z; psq[3]+=op.w*op.w;
            esum[0]+=oe.x; esum[1]+=oe.y; esum[2]+=oe.z; esum[3]+=oe.w;
            esq[0]+=oe.x*oe.x; esq[1]+=oe.y*oe.y; esq[2]+=oe.z*oe.z; esq[3]+=oe.w*oe.w;
        }
#pragma unroll
        for (int ci = 0; ci < 4; ci++) {
            atomicAdd(&sum_p[c4+ci], psum[ci]); atomicAdd(&sq_p[c4+ci], psq[ci]);
            atomicAdd(&sum_e[c4+ci], esum[ci]); atomicAdd(&sq_e[c4+ci], esq[ci]);
        }
    }
    __syncthreads();
    if (tid < 64) {
        atomicAdd(&g_stats[0][0][tid], sum_p[tid]); atomicAdd(&g_stats[0][1][tid], sq_p[tid]);
        atomicAdd(&g_stats[3][0][tid], sum_e[tid]); atomicAdd(&g_stats[3][1][tid], sq_e[tid]);
    }
}

// ---------------- paired layer jobs, 16-row tiles ----------------
__global__ void __launch_bounds__(256)
k_pair(const float* inA, int sAin, const float* wrA, const float* wlA,
       const float* bA, float* outA, int sAout,
       const float* inB, int sBin, const float* wrB, const float* wlB,
       const float* bB, float* outB, int sBout, int coutB) {
    bool isA = blockIdx.x < GB16;
    int blk = isA ? blockIdx.x : blockIdx.x - GB16;
    const float* in = isA ? inA : inB;
    int s_in  = isA ? sAin : sBin;
    const float* wr = isA ? wrA : wrB;
    const float* wl = isA ? wlA : wlB;
    const float* bias = isA ? bA : bB;
    float* out = isA ? outA : outB;
    int s_out = isA ? sAout : sBout;
    int cout  = isA ? 64 : coutB;

    __shared__ float ash[64 * ASTR];
    __shared__ float xsh[64 * ASTR];
    __shared__ float sc[64], tc[64], ssum[64], ssq[64];
    int tid = threadIdx.x;
    int row0 = blk * TR;

    if (tid < 64) {
        float s, t; bn_coef(s_in, tid, s, t);
        sc[tid] = s; tc[tid] = t;
        ssum[tid] = 0.f; ssq[tid] = 0.f;
    }
    __syncthreads();

    agg_tile256(in, row0, ash, sc, tc, tid);
    for (int idx = tid; idx < TR * 64; idx += 256) {
        int k = idx & 63, rr = idx >> 6;
        xsh[k * ASTR + rr] = fmaf(in[(size_t)(row0 + rr) * 64 + k], sc[k], tc[k]);
    }
    __syncthreads();

    if (cout == 64) {
        if (tid < 128) {
            int cg = tid & 15, rg = tid >> 4;
            int c4 = cg * 4, r2 = rg * 2;
            float acc[2][4] = {};
#pragma unroll 4
            for (int k = 0; k < 64; k++) {
                float a0 = ash[k * ASTR + r2];
                float a1 = ash[k * ASTR + r2 + 1];
                float x0 = xsh[k * ASTR + r2];
                float x1 = xsh[k * ASTR + r2 + 1];
                float4 w4 = __ldg((const float4*)(wr + k * 64 + c4));
                float4 l4 = __ldg((const float4*)(wl + k * 64 + c4));
                acc[0][0] = fmaf(a0, w4.x, fmaf(x0, l4.x, acc[0][0]));
                acc[0][1] = fmaf(a0, w4.y, fmaf(x0, l4.y, acc[0][1]));
                acc[0][2] = fmaf(a0, w4.z, fmaf(x0, l4.z, acc[0][2]));
                acc[0][3] = fmaf(a0, w4.w, fmaf(x0, l4.w, acc[0][3]));
                acc[1][0] = fmaf(a1, w4.x, fmaf(x1, l4.x, acc[1][0]));
                acc[1][1] = fmaf(a1, w4.y, fmaf(x1, l4.y, acc[1][1]));
                acc[1][2] = fmaf(a1, w4.z, fmaf(x1, l4.z, acc[1][2]));
                acc[1][3] = fmaf(a1, w4.w, fmaf(x1, l4.w, acc[1][3]));
            }
            float csum[4] = {}, csq[4] = {};
#pragma unroll
            for (int ri = 0; ri < 2; ri++) {
                int gr = row0 + r2 + ri;
                float v0 = fmaxf(acc[ri][0] + __ldg(&bias[c4+0]), 0.f);
                float v1 = fmaxf(acc[ri][1] + __ldg(&bias[c4+1]), 0.f);
                float v2 = fmaxf(acc[ri][2] + __ldg(&bias[c4+2]), 0.f);
                float v3 = fmaxf(acc[ri][3] + __ldg(&bias[c4+3]), 0.f);
                float4 o; o.x = v0; o.y = v1; o.z = v2; o.w = v3;
                *(float4*)&out[(size_t)gr * 64 + c4] = o;
                csum[0]+=v0; csum[1]+=v1; csum[2]+=v2; csum[3]+=v3;
                csq[0]+=v0*v0; csq[1]+=v1*v1; csq[2]+=v2*v2; csq[3]+=v3*v3;
            }
#pragma unroll
            for (int ci = 0; ci < 4; ci++) {
                atomicAdd(&ssum[c4+ci], csum[ci]);
                atomicAdd(&ssq[c4+ci], csq[ci]);
            }
        }
        __syncthreads();
        if (tid < 64) {
            atomicAdd(&g_stats[s_out][0][tid], ssum[tid]);
            atomicAdd(&g_stats[s_out][1][tid], ssq[tid]);
        }
    } else {
        // cout == 4: 16 rows x 4 cols = 64 active threads; W is (4,64) row-major
        if (tid < 64) {
            int r = tid >> 2, c = tid & 3;
            int gr = row0 + r;
            float acc = 0.f;
#pragma unroll 8
            for (int k = 0; k < 64; k++)
                acc = fmaf(ash[k*ASTR+r], __ldg(&wr[c*64 + k]),
                      fmaf(xsh[k*ASTR+r], __ldg(&wl[c*64 + k]), acc));
            float v = fmaxf(acc + __ldg(&bias[c]), 0.f);
            out[(size_t)gr * 4 + c] = v;
            atomicAdd(&ssum[c], v);
            atomicAdd(&ssq[c], v * v);
        }
        __syncthreads();
        if (tid < 4) {
            atomicAdd(&g_stats[s_out][0][tid], ssum[tid]);
            atomicAdd(&g_stats[s_out][1][tid], ssq[tid]);
        }
    }
}

// ---------------- pool assignment (750 blocks) + x_embed (375 blocks) --------
__global__ void k_pool_xemb(const float* __restrict__ plw, const float* __restrict__ plb,
                            const float* __restrict__ eb) {
    __shared__ float s1[64], t1[64], s2[64], t2[64], s3[4], t3[4];
    __shared__ float se[192], te[192];
    __shared__ float xsh[192 * ASTR];    // xemb branch: 16 rows x 192 ch (BN'd)
    int tid = threadIdx.x;

    if (blockIdx.x < 750) {
        if (tid < 64)       { float s,t; bn_coef(0, tid, s, t);      s1[tid]=s; t1[tid]=t; }
        else if (tid < 128) { float s,t; bn_coef(1, tid-64, s, t);   s2[tid-64]=s; t2[tid-64]=t; }
        else if (tid < 132) { float s,t; bn_coef(2, tid-128, s, t);  s3[tid-128]=s; t3[tid-128]=t; }
        __syncthreads();
        int i = blockIdx.x * 8 + (tid >> 5);
        int lane = tid & 31;
        float a0 = 0.f, a1 = 0.f, a2 = 0.f, a3 = 0.f;
        for (int k = lane; k < 64; k += 32) {
            float v1 = fmaf(g_p1[(size_t)i*64+k], s1[k], t1[k]);
            float v2 = fmaf(g_p2[(size_t)i*64+k], s2[k], t2[k]);
            a0 += v1 * plw[0*132+k] + v2 * plw[0*132+64+k];
            a1 += v1 * plw[1*132+k] + v2 * plw[1*132+64+k];
            a2 += v1 * plw[2*132+k] + v2 * plw[2*132+64+k];
            a3 += v1 * plw[3*132+k] + v2 * plw[3*132+64+k];
        }
        if (lane < 4) {
            float v3 = fmaf(g_p3[(size_t)i*4+lane], s3[lane], t3[lane]);
            a0 += v3 * plw[0*132+128+lane];
            a1 += v3 * plw[1*132+128+lane];
            a2 += v3 * plw[2*132+128+lane];
            a3 += v3 * plw[3*132+128+lane];
        }
#pragma unroll
        for (int o = 16; o > 0; o >>= 1) {
            a0 += __shfl_xor_sync(0xFFFFFFFFu, a0, o);
            a1 += __shfl_xor_sync(0xFFFFFFFFu, a1, o);
            a2 += __shfl_xor_sync(0xFFFFFFFFu, a2, o);
            a3 += __shfl_xor_sync(0xFFFFFFFFu, a3, o);
        }
        if (lane == 0) {
            float q0 = fmaxf(a0 + plb[0], 0.f), q1 = fmaxf(a1 + plb[1], 0.f);
            float q2 = fmaxf(a2 + plb[2], 0.f), q3 = fmaxf(a3 + plb[3], 0.f);
            int am = 0; float best = q0;
            if (q1 > best) { best = q1; am = 1; }
            if (q2 > best) { best = q2; am = 2; }
            if (q3 > best) { best = q3; am = 3; }
            g_am[i] = am;
            float e0 = expf(q0-best), e1 = expf(q1-best), e2 = expf(q2-best), e3 = expf(q3-best);
            float inv = 1.f / (e0+e1+e2+e3);
            g_ssm[i*4+0] = e0*inv; g_ssm[i*4+1] = e1*inv;
            g_ssm[i*4+2] = e2*inv; g_ssm[i*4+3] = e3*inv;
        }
    } else {
        if (tid < 192) {
            float s, t; bn_coef(3 + tid / 64, tid & 63, s, t);
            se[tid] = s; te[tid] = t;
        }
        __syncthreads();
        int blk = blockIdx.x - 750;          // 0..374
        int row0 = blk * 16;
        for (int idx = tid; idx < 1024; idx += 256) {
            int k = idx & 63, rr = idx >> 6;
            int gr = row0 + rr;
            xsh[k * ASTR + rr]        = fmaf(g_e1[(size_t)gr*64+k], se[k],     te[k]);
            xsh[(64+k) * ASTR + rr]   = fmaf(g_e2[(size_t)gr*64+k], se[64+k],  te[64+k]);
            xsh[(128+k) * ASTR + rr]  = fmaf(g_e3[(size_t)gr*64+k], se[128+k], te[128+k]);
        }
        __syncthreads();
        const float* wtx = g_wt + 10 * 4096;   // [k][c], 192 x 32
        if (tid < 128) {
            int rg = tid >> 3;          // 0..15 row
            int cg = tid & 7;           // 0..7 colgroup of 4
            int c4 = cg * 4;
            float acc0 = __ldg(&eb[c4+0]);
            float acc1 = __ldg(&eb[c4+1]);
            float acc2 = __ldg(&eb[c4+2]);
            float acc3 = __ldg(&eb[c4+3]);
#pragma unroll 8
            for (int k = 0; k < 192; k++) {
                float a = xsh[k * ASTR + rg];
                float4 w4 = __ldg((const float4*)(wtx + k * 32 + c4));
                acc0 = fmaf(a, w4.x, acc0);
                acc1 = fmaf(a, w4.y, acc1);
                acc2 = fmaf(a, w4.z, acc2);
                acc3 = fmaf(a, w4.w, acc3);
            }
            int gr = row0 + rg;
            float4 o; o.x = acc0; o.y = acc1; o.z = acc2; o.w = acc3;
            *(float4*)&g_xemb[(size_t)gr * 32 + c4] = o;
        }
    }
}

// s_x = softmax(S)^T @ BN(XE) -> [4,192], 250 blocks x 24 nodes
__global__ void k_sxacc() {
    int c = threadIdx.x;                  // 0..191
    int slot = 3 + c / 64, co = c & 63;
    float s, t; bn_coef(slot, co, s, t);
    const float* src = (c < 64) ? g_e1 : (c < 128) ? g_e2 : g_e3;
    int n0 = blockIdx.x * 24;
    float a0 = 0.f, a1 = 0.f, a2 = 0.f, a3 = 0.f;
#pragma unroll 4
    for (int n = n0; n < n0 + 24; n++) {
        float4 w = *(const float4*)&g_ssm[(size_t)n * 4];
        float v = fmaf(src[(size_t)n * 64 + co], s, t);
        a0 = fmaf(w.x, v, a0); a1 = fmaf(w.y, v, a1);
        a2 = fmaf(w.z, v, a2); a3 = fmaf(w.w, v, a3);
    }
    atomicAdd(&g_sx[0*192+c], a0);
    atomicAdd(&g_sx[1*192+c], a1);
    atomicAdd(&g_sx[2*192+c], a2);
    atomicAdd(&g_sx[3*192+c], a3);
}

__global__ void k_head(const float* __restrict__ l1w, const float* __restrict__ l1b,
                       const float* __restrict__ l2w, const float* __restrict__ l2b) {
    __shared__ float t1[4][64];
    int tid = threadIdx.x;
    int j = tid >> 6, c = tid & 63;
    float acc = l1b[c];
#pragma unroll 8
    for (int k = 0; k < 192; k++) acc = fmaf(g_sx[j*192+k], l1w[c*192+k], acc);
    t1[j][c] = fmaxf(acc, 0.f);
    __syncthreads();
    if (tid < 64) {
        int jj = tid >> 4, cc = tid & 15;
        float a = l2b[cc];
#pragma unroll
        for (int k = 0; k < 64; k++) a = fmaf(t1[jj][k], l2w[cc*64+k], a);
        g_sx2[jj*16+cc] = a;
    }
}

__global__ void k_final(const float* __restrict__ l3w, const float* __restrict__ l3b,
                        float* __restrict__ out) {
    __shared__ float w[768];
    __shared__ float b[16];
    __shared__ float sx2[64];
    int tid = threadIdx.x;
    for (int idx = tid; idx < 768; idx += 256) w[idx] = l3w[idx];
    if (tid < 16) b[tid] = l3b[tid];
    if (tid < 64) sx2[tid] = g_sx2[tid];
    __syncthreads();
    int c = tid & 15, ln = tid >> 4;
    int i = blockIdx.x * 16 + ln;
    int am = g_am[i];
    float acc = b[c];
    const float* xe = &g_xemb[(size_t)i * 32];
#pragma unroll
    for (int k = 0; k < 32; k++) acc = fmaf(xe[k], w[c*48+k], acc);
#pragma unroll
    for (int k = 0; k < 16; k++) acc = fmaf(sx2[am*16+k], w[c*48+32+k], acc);
    out[(size_t)i * 16 + c] = acc;
}

// ---------------- host ----------------
extern "C" void kernel_launch(void* const* d_in, const int* in_sizes, int n_in,
                              void* d_out, int out_size) {
    const int* ei = nullptr;
    const int* nt = nullptr;
    const float* P[29];
    int np = 0;
    for (int i = 0; i < n_in; i++) {
        if (in_sizes[i] == 2 * EE)      ei = (const int*)d_in[i];
        else if (in_sizes[i] == NN)     nt = (const int*)d_in[i];
        else if (np < 29)               P[np++] = (const float*)d_in[i];
    }
    if (!ei || !nt || np != 29) return;

    const float *emb  = P[0];
    const float *pw1r = P[1],  *pw1l = P[2],  *pb1 = P[3];
    const float *pw2r = P[4],  *pw2l = P[5],  *pb2 = P[6];
    const float *pw3r = P[7],  *pw3l = P[8],  *pb3 = P[9];
    const float *plw  = P[10], *plb  = P[11];
    const float *ew1r = P[12], *ew1l = P[13], *eb1 = P[14];
    const float *ew2r = P[15], *ew2l = P[16], *eb2 = P[17];
    const float *ew3r = P[18], *ew3l = P[19], *eb3 = P[20];
    const float *l1w  = P[21], *l1b  = P[22];
    const float *l2w  = P[23], *l2b  = P[24];
    const float *emblw = P[25], *emblb = P[26];
    const float *l3w  = P[27], *l3b  = P[28];
    float* out = (float*)d_out;

    static float *p_p1 = nullptr, *p_p2, *p_p3, *p_e1, *p_e2, *p_e3, *p_wt;
    if (!p_p1) {
        cudaGetSymbolAddress((void**)&p_p1, g_p1);
        cudaGetSymbolAddress((void**)&p_p2, g_p2);
        cudaGetSymbolAddress((void**)&p_p3, g_p3);
        cudaGetSymbolAddress((void**)&p_e1, g_e1);
        cudaGetSymbolAddress((void**)&p_e2, g_e2);
        cudaGetSymbolAddress((void**)&p_e3, g_e3);
        cudaGetSymbolAddress((void**)&p_wt, g_wt);
    }

    k_init<<<214, 256>>>(pw1r, pw1l, ew1r, ew1l, pw2r, pw2l, ew2r, ew2l,
                         ew3r, ew3l, emblw);
    k_build_gather<<<2250, 256>>>(ei, emb, nt);
    // layer 1: one agg, both outputs
    k_layer1<<<GB16, 256>>>(pb1, eb1);
    // layer 2 (pool + embed), transposed weights from g_wt
    k_pair<<<2 * GB16, 256>>>(p_p1, 0, p_wt + 4*4096, p_wt + 5*4096, pb2, p_p2, 1,
                              p_e1, 3, p_wt + 6*4096, p_wt + 7*4096, eb2, p_e2, 4, 64);
    // layer 3 (embed cout=64 + pool cout=4; pool uses original row-major weights)
    k_pair<<<2 * GB16, 256>>>(p_e2, 4, p_wt + 8*4096, p_wt + 9*4096, eb3, p_e3, 5,
                              p_p2, 1, pw3r, pw3l, pb3, p_p3, 2, 4);
    k_pool_xemb<<<1125, 256>>>(plw, plb, emblb);
    k_sxacc<<<250, 192>>>();
    k_head<<<1, 256>>>(l1w, l1b, l2w, l2b);
    k_final<<<NN / 16, 256>>>(l3w, l3b, out);
}

// round 12
// speedup vs baseline: 1.3330x; 1.0503x over previous
#include <cuda_runtime.h>
#include <math.h>

#define NN 6000
#define EE 192000
#define MAXDEG 128
#define BN_EPS 1e-5f
#define TR 16                // rows per tile
#define GB16 375             // NN / TR
#define NNINV (1.0f/6000.0f)
#define ASTR 17              // smem stride for 16-row tiles

// ---------------- scratch ----------------
__device__ int   g_cnt[NN];
__device__ int   g_slot[NN * MAXDEG];
__device__ float g_x0[NN * 64];
__device__ float g_p1[NN * 64];   // RAW (pre-BN) activations
__device__ float g_p2[NN * 64];
__device__ float g_p3[NN * 4];
__device__ float g_e1[NN * 64];
__device__ float g_e2[NN * 64];
__device__ float g_e3[NN * 64];
__device__ float g_wt[10 * 4096 + 6144]; // 10 transposed 64x64 + embl_w^T [192][32]
__device__ float g_stats[6][2][64];
__device__ float g_ssm[NN * 4];
__device__ int   g_am[NN];
__device__ float g_xemb[NN * 32];
__device__ float g_sx[4 * 192];
__device__ float g_sx2[4 * 16];

__device__ __forceinline__ void bn_coef(int slot, int c, float& s, float& t) {
    float m = g_stats[slot][0][c] * NNINV;
    float v = g_stats[slot][1][c] * NNINV - m * m;
    float sc = rsqrtf(fmaxf(v, 0.f) + BN_EPS);
    s = sc; t = -m * sc;
}

// ---------------- setup: zero + weight transposes ----------------
__global__ void k_init(const float* w0, const float* w1, const float* w2,
                       const float* w3, const float* w4, const float* w5,
                       const float* w6, const float* w7, const float* w8,
                       const float* w9, const float* wemb) {
    int b = blockIdx.x;
    if (b < 30) {
        int i = b * 256 + threadIdx.x;
        if (i < NN) g_cnt[i] = 0;
        else if (i < NN + 768) ((float*)g_stats)[i - NN] = 0.f;
        else if (i < NN + 1536) g_sx[i - NN - 768] = 0.f;
    } else if (b < 190) {
        const float* srcs[10] = {w0, w1, w2, w3, w4, w5, w6, w7, w8, w9};
        int bb = b - 30;
        int m = bb >> 4;
        int idx = ((bb & 15) * 256) + threadIdx.x;   // output index, [k][c]
        int k = idx >> 6, c = idx & 63;
        g_wt[m * 4096 + idx] = srcs[m][c * 64 + k];
    } else {
        int idx = (b - 190) * 256 + threadIdx.x;     // [0, 6144)
        int k = idx >> 5, c = idx & 31;              // [k][c], k<192, c<32
        g_wt[10 * 4096 + idx] = wemb[c * 192 + k];
    }
}

__global__ void k_build_gather(const int* __restrict__ ei,
                               const float* __restrict__ emb,
                               const int* __restrict__ nt) {
    int b = blockIdx.x;
    if (b < 750) {
        int e = b * 256 + threadIdx.x;
        int s = ei[e], d = ei[EE + e];
        int pos = atomicAdd(&g_cnt[s], 1);
        if (pos < MAXDEG) g_slot[s * MAXDEG + pos] = d;
    } else {
        int idx = (b - 750) * 256 + threadIdx.x;
        int i = idx >> 6, c = idx & 63;
        g_x0[idx] = emb[nt[i] * 64 + c];
    }
}

// ------- agg helper A (k_pair, 128 thr): 16 rows, 8 thr/row, 8 ch, deep MLP --
// Round-7 verified: 8 edges per iter, all slot indices loaded first, then 16
// independent float4 gathers in flight.
__device__ __forceinline__ void agg_tile_deep(const float* __restrict__ in, int row0,
                                              float* ash, const float* sc, const float* tc,
                                              int tid) {
    int r = tid >> 3;            // 0..15
    int q = tid & 7;             // channel group of 8
    int gr = row0 + r;
    int cnt = g_cnt[gr];
    if (cnt > MAXDEG) cnt = MAXDEG;
    const int* sl = g_slot + (size_t)gr * MAXDEG;
    int choff = q * 8;
    float4 a0 = {0,0,0,0}, a1 = {0,0,0,0};
    int j = 0;
    for (; j + 8 <= cnt; j += 8) {
        int i0 = sl[j+0], i1 = sl[j+1], i2 = sl[j+2], i3 = sl[j+3];
        int i4 = sl[j+4], i5 = sl[j+5], i6 = sl[j+6], i7 = sl[j+7];
        const float4* b0 = (const float4*)(in + (size_t)i0 * 64 + choff);
        const float4* b1 = (const float4*)(in + (size_t)i1 * 64 + choff);
        const float4* b2 = (const float4*)(in + (size_t)i2 * 64 + choff);
        const float4* b3 = (const float4*)(in + (size_t)i3 * 64 + choff);
        const float4* b4 = (const float4*)(in + (size_t)i4 * 64 + choff);
        const float4* b5 = (const float4*)(in + (size_t)i5 * 64 + choff);
        const float4* b6 = (const float4*)(in + (size_t)i6 * 64 + choff);
        const float4* b7 = (const float4*)(in + (size_t)i7 * 64 + choff);
        float4 u0 = b0[0], w0 = b0[1];
        float4 u1 = b1[0], w1 = b1[1];
        float4 u2 = b2[0], w2 = b2[1];
        float4 u3 = b3[0], w3 = b3[1];
        float4 u4 = b4[0], w4 = b4[1];
        float4 u5 = b5[0], w5 = b5[1];
        float4 u6 = b6[0], w6 = b6[1];
        float4 u7 = b7[0], w7 = b7[1];
        a0.x += (u0.x + u1.x) + (u2.x + u3.x) + (u4.x + u5.x) + (u6.x + u7.x);
        a0.y += (u0.y + u1.y) + (u2.y + u3.y) + (u4.y + u5.y) + (u6.y + u7.y);
        a0.z += (u0.z + u1.z) + (u2.z + u3.z) + (u4.z + u5.z) + (u6.z + u7.z);
        a0.w += (u0.w + u1.w) + (u2.w + u3.w) + (u4.w + u5.w) + (u6.w + u7.w);
        a1.x += (w0.x + w1.x) + (w2.x + w3.x) + (w4.x + w5.x) + (w6.x + w7.x);
        a1.y += (w0.y + w1.y) + (w2.y + w3.y) + (w4.y + w5.y) + (w6.y + w7.y);
        a1.z += (w0.z + w1.z) + (w2.z + w3.z) + (w4.z + w5.z) + (w6.z + w7.z);
        a1.w += (w0.w + w1.w) + (w2.w + w3.w) + (w4.w + w5.w) + (w6.w + w7.w);
    }
    if (j + 4 <= cnt) {
        int i0 = sl[j+0], i1 = sl[j+1], i2 = sl[j+2], i3 = sl[j+3];
        const float4* b0 = (const float4*)(in + (size_t)i0 * 64 + choff);
        const float4* b1 = (const float4*)(in + (size_t)i1 * 64 + choff);
        const float4* b2 = (const float4*)(in + (size_t)i2 * 64 + choff);
        const float4* b3 = (const float4*)(in + (size_t)i3 * 64 + choff);
        float4 u0 = b0[0], w0 = b0[1];
        float4 u1 = b1[0], w1 = b1[1];
        float4 u2 = b2[0], w2 = b2[1];
        float4 u3 = b3[0], w3 = b3[1];
        a0.x += (u0.x + u1.x) + (u2.x + u3.x);
        a0.y += (u0.y + u1.y) + (u2.y + u3.y);
        a0.z += (u0.z + u1.z) + (u2.z + u3.z);
        a0.w += (u0.w + u1.w) + (u2.w + u3.w);
        a1.x += (w0.x + w1.x) + (w2.x + w3.x);
        a1.y += (w0.y + w1.y) + (w2.y + w3.y);
        a1.z += (w0.z + w1.z) + (w2.z + w3.z);
        a1.w += (w0.w + w1.w) + (w2.w + w3.w);
        j += 4;
    }
    for (; j < cnt; j++) {
        const float4* b0 = (const float4*)(in + (size_t)sl[j] * 64 + choff);
        float4 u0 = b0[0], w0 = b0[1];
        a0.x += u0.x; a0.y += u0.y; a0.z += u0.z; a0.w += u0.w;
        a1.x += w0.x; a1.y += w0.y; a1.z += w0.z; a1.w += w0.w;
    }
    float vals[8] = {a0.x, a0.y, a0.z, a0.w, a1.x, a1.y, a1.z, a1.w};
    if (cnt > 0) {
        float inv = 1.f / (float)cnt;
#pragma unroll
        for (int u = 0; u < 8; u++) {
            int ch = choff + u;
            ash[ch * ASTR + r] = fmaf(vals[u] * inv, sc[ch], tc[ch]);
        }
    } else {
#pragma unroll
        for (int u = 0; u < 8; u++) ash[(choff + u) * ASTR + r] = 0.f;
    }
}

// ------- agg helper B (k_layer1, 256 thr): 16 rows, 16 thr/row, 4 ch ---------
__device__ __forceinline__ void agg_tile256(const float* __restrict__ in, int row0,
                                            float* ash, const float* sc, const float* tc,
                                            int tid) {
    int r = tid >> 4;            // 0..15
    int q = tid & 15;            // channel group of 4
    int gr = row0 + r;
    int cnt = g_cnt[gr];
    if (cnt > MAXDEG) cnt = MAXDEG;
    const int* sl = g_slot + (size_t)gr * MAXDEG;
    int choff = q * 4;
    float4 a = {0, 0, 0, 0};
    int j = 0;
    for (; j + 4 <= cnt; j += 4) {
        int i0 = sl[j], i1 = sl[j+1], i2 = sl[j+2], i3 = sl[j+3];
        float4 u0 = *(const float4*)(in + (size_t)i0 * 64 + choff);
        float4 u1 = *(const float4*)(in + (size_t)i1 * 64 + choff);
        float4 u2 = *(const float4*)(in + (size_t)i2 * 64 + choff);
        float4 u3 = *(const float4*)(in + (size_t)i3 * 64 + choff);
        a.x += (u0.x + u1.x) + (u2.x + u3.x);
        a.y += (u0.y + u1.y) + (u2.y + u3.y);
        a.z += (u0.z + u1.z) + (u2.z + u3.z);
        a.w += (u0.w + u1.w) + (u2.w + u3.w);
    }
    for (; j < cnt; j++) {
        float4 u0 = *(const float4*)(in + (size_t)sl[j] * 64 + choff);
        a.x += u0.x; a.y += u0.y; a.z += u0.z; a.w += u0.w;
    }
    if (cnt > 0) {
        float inv = 1.f / (float)cnt;
        ash[(choff+0) * ASTR + r] = fmaf(a.x * inv, sc[choff+0], tc[choff+0]);
        ash[(choff+1) * ASTR + r] = fmaf(a.y * inv, sc[choff+1], tc[choff+1]);
        ash[(choff+2) * ASTR + r] = fmaf(a.z * inv, sc[choff+2], tc[choff+2]);
        ash[(choff+3) * ASTR + r] = fmaf(a.w * inv, sc[choff+3], tc[choff+3]);
    } else {
#pragma unroll
        for (int u = 0; u < 4; u++) ash[(choff + u) * ASTR + r] = 0.f;
    }
}

// ---------------- layer 1: dual output from one agg (round-11, 256 thr) ------
__global__ void __launch_bounds__(256)
k_layer1(const float* __restrict__ pb, const float* __restrict__ eb) {
    const float* pwr = g_wt + 0 * 4096;
    const float* pwl = g_wt + 1 * 4096;
    const float* ewr = g_wt + 2 * 4096;
    const float* ewl = g_wt + 3 * 4096;
    __shared__ float ash[64 * ASTR];
    __shared__ float xsh[64 * ASTR];
    __shared__ float idc[64];
    __shared__ float zc[64];
    __shared__ float sum_p[64], sq_p[64], sum_e[64], sq_e[64];
    int tid = threadIdx.x;
    int row0 = blockIdx.x * TR;

    if (tid < 64) {
        idc[tid] = 1.f; zc[tid] = 0.f;
        sum_p[tid] = 0.f; sq_p[tid] = 0.f; sum_e[tid] = 0.f; sq_e[tid] = 0.f;
    }
    __syncthreads();

    agg_tile256(g_x0, row0, ash, idc, zc, tid);
    for (int idx = tid; idx < TR * 64; idx += 256) {
        int k = idx & 63, rr = idx >> 6;
        xsh[k * ASTR + rr] = g_x0[(size_t)(row0 + rr) * 64 + k];
    }
    __syncthreads();

    if (tid < 128) {
        int cg = tid & 15, rg = tid >> 4;     // 16 colgroups x 8 rowgroups
        int c4 = cg * 4, r2 = rg * 2;
        float accp[2][4] = {}, acce[2][4] = {};
#pragma unroll 4
        for (int k = 0; k < 64; k++) {
            float a0 = ash[k * ASTR + r2];
            float a1 = ash[k * ASTR + r2 + 1];
            float x0 = xsh[k * ASTR + r2];
            float x1 = xsh[k * ASTR + r2 + 1];
            float4 pr = __ldg((const float4*)(pwr + k * 64 + c4));
            float4 pl = __ldg((const float4*)(pwl + k * 64 + c4));
            float4 er = __ldg((const float4*)(ewr + k * 64 + c4));
            float4 el = __ldg((const float4*)(ewl + k * 64 + c4));
            accp[0][0] = fmaf(a0, pr.x, fmaf(x0, pl.x, accp[0][0]));
            accp[0][1] = fmaf(a0, pr.y, fmaf(x0, pl.y, accp[0][1]));
            accp[0][2] = fmaf(a0, pr.z, fmaf(x0, pl.z, accp[0][2]));
            accp[0][3] = fmaf(a0, pr.w, fmaf(x0, pl.w, accp[0][3]));
            accp[1][0] = fmaf(a1, pr.x, fmaf(x1, pl.x, accp[1][0]));
            accp[1][1] = fmaf(a1, pr.y, fmaf(x1, pl.y, accp[1][1]));
            accp[1][2] = fmaf(a1, pr.z, fmaf(x1, pl.z, accp[1][2]));
            accp[1][3] = fmaf(a1, pr.w, fmaf(x1, pl.w, accp[1][3]));
            acce[0][0] = fmaf(a0, er.x, fmaf(x0, el.x, acce[0][0]));
            acce[0][1] = fmaf(a0, er.y, fmaf(x0, el.y, acce[0][1]));
            acce[0][2] = fmaf(a0, er.z, fmaf(x0, el.z, acce[0][2]));
            acce[0][3] = fmaf(a0, er.w, fmaf(x0, el.w, acce[0][3]));
            acce[1][0] = fmaf(a1, er.x, fmaf(x1, el.x, acce[1][0]));
            acce[1][1] = fmaf(a1, er.y, fmaf(x1, el.y, acce[1][1]));
            acce[1][2] = fmaf(a1, er.z, fmaf(x1, el.z, acce[1][2]));
            acce[1][3] = fmaf(a1, er.w, fmaf(x1, el.w, acce[1][3]));
        }
        float psum[4] = {}, psq[4] = {}, esum[4] = {}, esq[4] = {};
#pragma unroll
        for (int ri = 0; ri < 2; ri++) {
            int gr = row0 + r2 + ri;
            float4 op, oe;
            op.x = fmaxf(accp[ri][0] + __ldg(&pb[c4+0]), 0.f);
            op.y = fmaxf(accp[ri][1] + __ldg(&pb[c4+1]), 0.f);
            op.z = fmaxf(accp[ri][2] + __ldg(&pb[c4+2]), 0.f);
            op.w = fmaxf(accp[ri][3] + __ldg(&pb[c4+3]), 0.f);
            oe.x = fmaxf(acce[ri][0] + __ldg(&eb[c4+0]), 0.f);
            oe.y = fmaxf(acce[ri][1] + __ldg(&eb[c4+1]), 0.f);
            oe.z = fmaxf(acce[ri][2] + __ldg(&eb[c4+2]), 0.f);
            oe.w = fmaxf(acce[ri][3] + __ldg(&eb[c4+3]), 0.f);
            *(float4*)&g_p1[(size_t)gr * 64 + c4] = op;
            *(float4*)&g_e1[(size_t)gr * 64 + c4] = oe;
            psum[0]+=op.x; psum[1]+=op.y; psum[2]+=op.z; psum[3]+=op.w;
            psq[0]+=op.x*op.x; psq[1]+=op.y*op.y; psq[2]+=op.z*op.z; psq[3]+=op.w*op.w;
            esum[0]+=oe.x; esum[1]+=oe.y; esum[2]+=oe.z; esum[3]+=oe.w;
            esq[0]+=oe.x*oe.x; esq[1]+=oe.y*oe.y; esq[2]+=oe.z*oe.z; esq[3]+=oe.w*oe.w;
        }
#pragma unroll
        for (int ci = 0; ci < 4; ci++) {
            atomicAdd(&sum_p[c4+ci], psum[ci]); atomicAdd(&sq_p[c4+ci], psq[ci]);
            atomicAdd(&sum_e[c4+ci], esum[ci]); atomicAdd(&sq_e[c4+ci], esq[ci]);
        }
    }
    __syncthreads();
    if (tid < 64) {
        atomicAdd(&g_stats[0][0][tid], sum_p[tid]); atomicAdd(&g_stats[0][1][tid], sq_p[tid]);
        atomicAdd(&g_stats[3][0][tid], sum_e[tid]); atomicAdd(&g_stats[3][1][tid], sq_e[tid]);
    }
}

// ---------------- paired layer jobs, 16-row tiles (round-7, 128 thr) ---------
__global__ void __launch_bounds__(128)
k_pair(const float* inA, int sAin, const float* wrA, const float* wlA,
       const float* bA, float* outA, int sAout,
       const float* inB, int sBin, const float* wrB, const float* wlB,
       const float* bB, float* outB, int sBout, int coutB) {
    bool isA = blockIdx.x < GB16;
    int blk = isA ? blockIdx.x : blockIdx.x - GB16;
    const float* in = isA ? inA : inB;
    int s_in  = isA ? sAin : sBin;
    const float* wr = isA ? wrA : wrB;
    const float* wl = isA ? wlA : wlB;
    const float* bias = isA ? bA : bB;
    float* out = isA ? outA : outB;
    int s_out = isA ? sAout : sBout;
    int cout  = isA ? 64 : coutB;

    __shared__ float ash[64 * ASTR];
    __shared__ float xsh[64 * ASTR];
    __shared__ float sc[64], tc[64], ssum[64], ssq[64];
    int tid = threadIdx.x;
    int row0 = blk * TR;

    if (tid < 64) {
        float s, t; bn_coef(s_in, tid, s, t);
        sc[tid] = s; tc[tid] = t;
        ssum[tid] = 0.f; ssq[tid] = 0.f;
    }
    __syncthreads();

    agg_tile_deep(in, row0, ash, sc, tc, tid);
    for (int idx = tid; idx < TR * 64; idx += 128) {
        int k = idx & 63, rr = idx >> 6;
        xsh[k * ASTR + rr] = fmaf(in[(size_t)(row0 + rr) * 64 + k], sc[k], tc[k]);
    }
    __syncthreads();

    if (cout == 64) {
        int cg = tid & 15, rg = tid >> 4;
        int c4 = cg * 4, r2 = rg * 2;
        float acc[2][4] = {};
#pragma unroll 4
        for (int k = 0; k < 64; k++) {
            float a0 = ash[k * ASTR + r2];
            float a1 = ash[k * ASTR + r2 + 1];
            float x0 = xsh[k * ASTR + r2];
            float x1 = xsh[k * ASTR + r2 + 1];
            float4 w4 = __ldg((const float4*)(wr + k * 64 + c4));
            float4 l4 = __ldg((const float4*)(wl + k * 64 + c4));
            acc[0][0] = fmaf(a0, w4.x, fmaf(x0, l4.x, acc[0][0]));
            acc[0][1] = fmaf(a0, w4.y, fmaf(x0, l4.y, acc[0][1]));
            acc[0][2] = fmaf(a0, w4.z, fmaf(x0, l4.z, acc[0][2]));
            acc[0][3] = fmaf(a0, w4.w, fmaf(x0, l4.w, acc[0][3]));
            acc[1][0] = fmaf(a1, w4.x, fmaf(x1, l4.x, acc[1][0]));
            acc[1][1] = fmaf(a1, w4.y, fmaf(x1, l4.y, acc[1][1]));
            acc[1][2] = fmaf(a1, w4.z, fmaf(x1, l4.z, acc[1][2]));
            acc[1][3] = fmaf(a1, w4.w, fmaf(x1, l4.w, acc[1][3]));
        }
        float csum[4] = {}, csq[4] = {};
#pragma unroll
        for (int ri = 0; ri < 2; ri++) {
            int gr = row0 + r2 + ri;
            float v0 = fmaxf(acc[ri][0] + __ldg(&bias[c4+0]), 0.f);
            float v1 = fmaxf(acc[ri][1] + __ldg(&bias[c4+1]), 0.f);
            float v2 = fmaxf(acc[ri][2] + __ldg(&bias[c4+2]), 0.f);
            float v3 = fmaxf(acc[ri][3] + __ldg(&bias[c4+3]), 0.f);
            float4 o; o.x = v0; o.y = v1; o.z = v2; o.w = v3;
            *(float4*)&out[(size_t)gr * 64 + c4] = o;
            csum[0]+=v0; csum[1]+=v1; csum[2]+=v2; csum[3]+=v3;
            csq[0]+=v0*v0; csq[1]+=v1*v1; csq[2]+=v2*v2; csq[3]+=v3*v3;
        }
#pragma unroll
        for (int ci = 0; ci < 4; ci++) {
            atomicAdd(&ssum[c4+ci], csum[ci]);
            atomicAdd(&ssq[c4+ci], csq[ci]);
        }
        __syncthreads();
        if (tid < 64) {
            atomicAdd(&g_stats[s_out][0][tid], ssum[tid]);
            atomicAdd(&g_stats[s_out][1][tid], ssq[tid]);
        }
    } else {
        // cout == 4: 16 rows x 4 cols = 64 active threads; W is (4,64) row-major
        if (tid < 64) {
            int r = tid >> 2, c = tid & 3;
            int gr = row0 + r;
            float acc = 0.f;
#pragma unroll 8
            for (int k = 0; k < 64; k++)
                acc = fmaf(ash[k*ASTR+r], __ldg(&wr[c*64 + k]),
                      fmaf(xsh[k*ASTR+r], __ldg(&wl[c*64 + k]), acc));
            float v = fmaxf(acc + __ldg(&bias[c]), 0.f);
            out[(size_t)gr * 4 + c] = v;
            atomicAdd(&ssum[c], v);
            atomicAdd(&ssq[c], v * v);
        }
        __syncthreads();
        if (tid < 4) {
            atomicAdd(&g_stats[s_out][0][tid], ssum[tid]);
            atomicAdd(&g_stats[s_out][1][tid], ssq[tid]);
        }
    }
}

// ---------------- pool assignment (750 blocks) + x_embed (375 blocks) --------
__global__ void k_pool_xemb(const float* __restrict__ plw, const float* __restrict__ plb,
                            const float* __restrict__ eb) {
    __shared__ float s1[64], t1[64], s2[64], t2[64], s3[4], t3[4];
    __shared__ float se[192], te[192];
    __shared__ float xsh[192 * ASTR];    // xemb branch: 16 rows x 192 ch (BN'd)
    int tid = threadIdx.x;

    if (blockIdx.x < 750) {
        if (tid < 64)       { float s,t; bn_coef(0, tid, s, t);      s1[tid]=s; t1[tid]=t; }
        else if (tid < 128) { float s,t; bn_coef(1, tid-64, s, t);   s2[tid-64]=s; t2[tid-64]=t; }
        else if (tid < 132) { float s,t; bn_coef(2, tid-128, s, t);  s3[tid-128]=s; t3[tid-128]=t; }
        __syncthreads();
        int i = blockIdx.x * 8 + (tid >> 5);
        int lane = tid & 31;
        float a0 = 0.f, a1 = 0.f, a2 = 0.f, a3 = 0.f;
        for (int k = lane; k < 64; k += 32) {
            float v1 = fmaf(g_p1[(size_t)i*64+k], s1[k], t1[k]);
            float v2 = fmaf(g_p2[(size_t)i*64+k], s2[k], t2[k]);
            a0 += v1 * plw[0*132+k] + v2 * plw[0*132+64+k];
            a1 += v1 * plw[1*132+k] + v2 * plw[1*132+64+k];
            a2 += v1 * plw[2*132+k] + v2 * plw[2*132+64+k];
            a3 += v1 * plw[3*132+k] + v2 * plw[3*132+64+k];
        }
        if (lane < 4) {
            float v3 = fmaf(g_p3[(size_t)i*4+lane], s3[lane], t3[lane]);
            a0 += v3 * plw[0*132+128+lane];
            a1 += v3 * plw[1*132+128+lane];
            a2 += v3 * plw[2*132+128+lane];
            a3 += v3 * plw[3*132+128+lane];
        }
#pragma unroll
        for (int o = 16; o > 0; o >>= 1) {
            a0 += __shfl_xor_sync(0xFFFFFFFFu, a0, o);
            a1 += __shfl_xor_sync(0xFFFFFFFFu, a1, o);
            a2 += __shfl_xor_sync(0xFFFFFFFFu, a2, o);
            a3 += __shfl_xor_sync(0xFFFFFFFFu, a3, o);
        }
        if (lane == 0) {
            float q0 = fmaxf(a0 + plb[0], 0.f), q1 = fmaxf(a1 + plb[1], 0.f);
            float q2 = fmaxf(a2 + plb[2], 0.f), q3 = fmaxf(a3 + plb[3], 0.f);
            int am = 0; float best = q0;
            if (q1 > best) { best = q1; am = 1; }
            if (q2 > best) { best = q2; am = 2; }
            if (q3 > best) { best = q3; am = 3; }
            g_am[i] = am;
            float e0 = expf(q0-best), e1 = expf(q1-best), e2 = expf(q2-best), e3 = expf(q3-best);
            float inv = 1.f / (e0+e1+e2+e3);
            g_ssm[i*4+0] = e0*inv; g_ssm[i*4+1] = e1*inv;
            g_ssm[i*4+2] = e2*inv; g_ssm[i*4+3] = e3*inv;
        }
    } else {
        if (tid < 192) {
            float s, t; bn_coef(3 + tid / 64, tid & 63, s, t);
            se[tid] = s; te[tid] = t;
        }
        __syncthreads();
        int blk = blockIdx.x - 750;          // 0..374
        int row0 = blk * 16;
        for (int idx = tid; idx < 1024; idx += 256) {
            int k = idx & 63, rr = idx >> 6;
            int gr = row0 + rr;
            xsh[k * ASTR + rr]        = fmaf(g_e1[(size_t)gr*64+k], se[k],     te[k]);
            xsh[(64+k) * ASTR + rr]   = fmaf(g_e2[(size_t)gr*64+k], se[64+k],  te[64+k]);
            xsh[(128+k) * ASTR + rr]  = fmaf(g_e3[(size_t)gr*64+k], se[128+k], te[128+k]);
        }
        __syncthreads();
        const float* wtx = g_wt + 10 * 4096;   // [k][c], 192 x 32
        if (tid < 128) {
            int rg = tid >> 3;          // 0..15 row
            int cg = tid & 7;           // 0..7 colgroup of 4
            int c4 = cg * 4;
            float acc0 = __ldg(&eb[c4+0]);
            float acc1 = __ldg(&eb[c4+1]);
            float acc2 = __ldg(&eb[c4+2]);
            float acc3 = __ldg(&eb[c4+3]);
#pragma unroll 8
            for (int k = 0; k < 192; k++) {
                float a = xsh[k * ASTR + rg];
                float4 w4 = __ldg((const float4*)(wtx + k * 32 + c4));
                acc0 = fmaf(a, w4.x, acc0);
                acc1 = fmaf(a, w4.y, acc1);
                acc2 = fmaf(a, w4.z, acc2);
                acc3 = fmaf(a, w4.w, acc3);
            }
            int gr = row0 + rg;
            float4 o; o.x = acc0; o.y = acc1; o.z = acc2; o.w = acc3;
            *(float4*)&g_xemb[(size_t)gr * 32 + c4] = o;
        }
    }
}

// s_x = softmax(S)^T @ BN(XE) -> [4,192], 250 blocks x 24 nodes
__global__ void k_sxacc() {
    int c = threadIdx.x;                  // 0..191
    int slot = 3 + c / 64, co = c & 63;
    float s, t; bn_coef(slot, co, s, t);
    const float* src = (c < 64) ? g_e1 : (c < 128) ? g_e2 : g_e3;
    int n0 = blockIdx.x * 24;
    float a0 = 0.f, a1 = 0.f, a2 = 0.f, a3 = 0.f;
#pragma unroll 4
    for (int n = n0; n < n0 + 24; n++) {
        float4 w = *(const float4*)&g_ssm[(size_t)n * 4];
        float v = fmaf(src[(size_t)n * 64 + co], s, t);
        a0 = fmaf(w.x, v, a0); a1 = fmaf(w.y, v, a1);
        a2 = fmaf(w.z, v, a2); a3 = fmaf(w.w, v, a3);
    }
    atomicAdd(&g_sx[0*192+c], a0);
    atomicAdd(&g_sx[1*192+c], a1);
    atomicAdd(&g_sx[2*192+c], a2);
    atomicAdd(&g_sx[3*192+c], a3);
}

__global__ void k_head(const float* __restrict__ l1w, const float* __restrict__ l1b,
                       const float* __restrict__ l2w, const float* __restrict__ l2b) {
    __shared__ float t1[4][64];
    int tid = threadIdx.x;
    int j = tid >> 6, c = tid & 63;
    float acc = l1b[c];
#pragma unroll 8
    for (int k = 0; k < 192; k++) acc = fmaf(g_sx[j*192+k], l1w[c*192+k], acc);
    t1[j][c] = fmaxf(acc, 0.f);
    __syncthreads();
    if (tid < 64) {
        int jj = tid >> 4, cc = tid & 15;
        float a = l2b[cc];
#pragma unroll
        for (int k = 0; k < 64; k++) a = fmaf(t1[jj][k], l2w[cc*64+k], a);
        g_sx2[jj*16+cc] = a;
    }
}

__global__ void k_final(const float* __restrict__ l3w, const float* __restrict__ l3b,
                        float* __restrict__ out) {
    __shared__ float w[768];
    __shared__ float b[16];
    __shared__ float sx2[64];
    int tid = threadIdx.x;
    for (int idx = tid; idx < 768; idx += 256) w[idx] = l3w[idx];
    if (tid < 16) b[tid] = l3b[tid];
    if (tid < 64) sx2[tid] = g_sx2[tid];
    __syncthreads();
    int c = tid & 15, ln = tid >> 4;
    int i = blockIdx.x * 16 + ln;
    int am = g_am[i];
    float acc = b[c];
    const float* xe = &g_xemb[(size_t)i * 32];
#pragma unroll
    for (int k = 0; k < 32; k++) acc = fmaf(xe[k], w[c*48+k], acc);
#pragma unroll
    for (int k = 0; k < 16; k++) acc = fmaf(sx2[am*16+k], w[c*48+32+k], acc);
    out[(size_t)i * 16 + c] = acc;
}

// ---------------- host ----------------
extern "C" void kernel_launch(void* const* d_in, const int* in_sizes, int n_in,
                              void* d_out, int out_size) {
    const int* ei = nullptr;
    const int* nt = nullptr;
    const float* P[29];
    int np = 0;
    for (int i = 0; i < n_in; i++) {
        if (in_sizes[i] == 2 * EE)      ei = (const int*)d_in[i];
        else if (in_sizes[i] == NN)     nt = (const int*)d_in[i];
        else if (np < 29)               P[np++] = (const float*)d_in[i];
    }
    if (!ei || !nt || np != 29) return;

    const float *emb  = P[0];
    const float *pw1r = P[1],  *pw1l = P[2],  *pb1 = P[3];
    const float *pw2r = P[4],  *pw2l = P[5],  *pb2 = P[6];
    const float *pw3r = P[7],  *pw3l = P[8],  *pb3 = P[9];
    const float *plw  = P[10], *plb  = P[11];
    const float *ew1r = P[12], *ew1l = P[13], *eb1 = P[14];
    const float *ew2r = P[15], *ew2l = P[16], *eb2 = P[17];
    const float *ew3r = P[18], *ew3l = P[19], *eb3 = P[20];
    const float *l1w  = P[21], *l1b  = P[22];
    const float *l2w  = P[23], *l2b  = P[24];
    const float *emblw = P[25], *emblb = P[26];
    const float *l3w  = P[27], *l3b  = P[28];
    float* out = (float*)d_out;

    static float *p_p1 = nullptr, *p_p2, *p_p3, *p_e1, *p_e2, *p_e3, *p_wt;
    if (!p_p1) {
        cudaGetSymbolAddress((void**)&p_p1, g_p1);
        cudaGetSymbolAddress((void**)&p_p2, g_p2);
        cudaGetSymbolAddress((void**)&p_p3, g_p3);
        cudaGetSymbolAddress((void**)&p_e1, g_e1);
        cudaGetSymbolAddress((void**)&p_e2, g_e2);
        cudaGetSymbolAddress((void**)&p_e3, g_e3);
        cudaGetSymbolAddress((void**)&p_wt, g_wt);
    }

    k_init<<<214, 256>>>(pw1r, pw1l, ew1r, ew1l, pw2r, pw2l, ew2r, ew2l,
                         ew3r, ew3l, emblw);
    k_build_gather<<<2250, 256>>>(ei, emb, nt);
    // layer 1: one agg, both outputs (256 thr)
    k_layer1<<<GB16, 256>>>(pb1, eb1);
    // layer 2 (pool + embed), transposed weights from g_wt (128 thr, deep agg)
    k_pair<<<2 * GB16, 128>>>(p_p1, 0, p_wt + 4*4096, p_wt + 5*4096, pb2, p_p2, 1,
                              p_e1, 3, p_wt + 6*4096, p_wt + 7*4096, eb2, p_e2, 4, 64);
    // layer 3 (embed cout=64 + pool cout=4; pool uses original row-major weights)
    k_pair<<<2 * GB16, 128>>>(p_e2, 4, p_wt + 8*4096, p_wt + 9*4096, eb3, p_e3, 5,
                              p_p2, 1, pw3r, pw3l, pb3, p_p3, 2, 4);
    k_pool_xemb<<<1125, 256>>>(plw, plb, emblb);
    k_sxacc<<<250, 192>>>();
    k_head<<<1, 256>>>(l1w, l1b, l2w, l2b);
    k_final<<<NN / 16, 256>>>(l3w, l3b, out);
}